// round 1
// baseline (speedup 1.0000x reference)
#include <cuda_runtime.h>
#include <math.h>

#define N_ENT 100000
#define N_REL 12
#define DD 64
#define NE 1000000
#define OUTD 160   // 64 + 64 + 32

// ---------------- device scratch (no allocations allowed) ----------------
__device__ float g_proj[(size_t)N_ENT * N_REL * DD];   // 307.2 MB
__device__ float g_logits[NE];                          // logits -> ex (reused)
__device__ float g_m[N_ENT];
__device__ float g_den[N_ENT];
__device__ float g_hn0[(size_t)N_ENT * DD];
__device__ float g_hn1[(size_t)N_ENT * DD];

// ---------------- helpers ----------------
__device__ __forceinline__ void atomicMaxF(float* addr, float v) {
    int old = __float_as_int(*addr);
    while (v > __int_as_float(old)) {
        int assumed = old;
        old = atomicCAS((int*)addr, assumed, __float_as_int(v));
        if (old == assumed) break;
    }
}

__device__ __forceinline__ float dot4(float4 a, float4 b) {
    return a.x * b.x + a.y * b.y + a.z * b.z + a.w * b.w;
}

__device__ __forceinline__ float leaky(float x) {
    return x > 0.0f ? x : 0.01f * x;
}

// ---------------- init ----------------
__global__ void k_init() {
    int i = blockIdx.x * blockDim.x + threadIdx.x;
    if (i < N_ENT * DD) { g_hn0[i] = 0.0f; g_hn1[i] = 0.0f; }
    if (i < N_ENT)      { g_m[i] = -INFINITY; g_den[i] = 0.0f; }
}

// ---------------- proj[n,r,:] = emb[n,:] @ W_r[r,:,:] ----------------
// block: 256 threads = (vg 0..3) x (j 0..63); 16 nodes per tile, grid-stride tiles.
__global__ void k_proj(const float* __restrict__ emb, const float* __restrict__ Wr) {
    __shared__ float Wt[DD][68];      // W transposed: Wt[j][d], padded pitch 68
    __shared__ float es[16][DD];      // 16 node embeddings

    const int r = blockIdx.y;
    const int tid = threadIdx.x;

    for (int idx = tid; idx < DD * DD; idx += 256) {
        int d = idx >> 6, j = idx & 63;
        Wt[j][d] = Wr[(size_t)r * DD * DD + idx];
    }
    __syncthreads();

    const int j = tid & 63, vg = tid >> 6;
    const int NTILES = N_ENT / 16;   // 6250 exactly

    for (int t = blockIdx.x; t < NTILES; t += gridDim.x) {
        int n0 = t * 16;
        // load 16 emb rows: 256 float4s, one per thread
        {
            int v = tid >> 4, q = tid & 15;
            ((float4*)es[v])[q] = ((const float4*)(emb + (size_t)(n0 + v) * DD))[q];
        }
        __syncthreads();

        float acc[4] = {0.f, 0.f, 0.f, 0.f};
#pragma unroll
        for (int d4 = 0; d4 < 16; d4++) {
            float4 w = *(const float4*)&Wt[j][d4 * 4];
#pragma unroll
            for (int v = 0; v < 4; v++) {
                float4 e = *(const float4*)&es[vg * 4 + v][d4 * 4];
                acc[v] += dot4(e, w);
            }
        }
#pragma unroll
        for (int v = 0; v < 4; v++) {
            int n = n0 + vg * 4 + v;
            g_proj[((size_t)n * N_REL + r) * DD + j] = acc[v];
        }
        __syncthreads();
    }
}

// ---------------- per-edge logits + segment max (fused) ----------------
// 1 warp per edge, 8 edges per block.
__global__ void k_logits(const float* __restrict__ rel_emb,
                         const int* __restrict__ src, const int* __restrict__ dst,
                         const int* __restrict__ et) {
    int e = blockIdx.x * 8 + (threadIdx.x >> 5);
    if (e >= NE) return;
    int l = threadIdx.x & 31;
    int s = src[e], d = dst[e], r = et[e];
    const float* pt = g_proj + ((size_t)s * N_REL + r) * DD;
    const float* ph = g_proj + ((size_t)d * N_REL + r) * DD;
    const float* pr = rel_emb + (size_t)r * DD;

    float sum = pt[l]      * tanhf(ph[l]      + pr[l])
              + pt[l + 32] * tanhf(ph[l + 32] + pr[l + 32]);
#pragma unroll
    for (int o = 16; o; o >>= 1) sum += __shfl_xor_sync(0xffffffffu, sum, o);
    if (l == 0) {
        g_logits[e] = sum;
        atomicMaxF(&g_m[d], sum);
    }
}

// ---------------- ex = exp(logit - m[dst]); den[dst] += ex ----------------
__global__ void k_exp(const int* __restrict__ dst) {
    int e = blockIdx.x * 256 + threadIdx.x;
    if (e >= NE) return;
    int d = dst[e];
    float ex = expf(g_logits[e] - g_m[d]);
    g_logits[e] = ex;                 // overwrite logits with ex
    atomicAdd(&g_den[d], ex);
}

// ---------------- hn[dst] += x[src] * att  (64 threads per edge) ----------
__global__ void k_scatter(const float* __restrict__ x, int pitch, int which,
                          const int* __restrict__ src, const int* __restrict__ dst) {
    int e = blockIdx.x * 4 + (threadIdx.x >> 6);
    if (e >= NE) return;
    int j = threadIdx.x & 63;
    int s = src[e], d = dst[e];
    float att = g_logits[e] / g_den[d];
    float* hn = which ? g_hn1 : g_hn0;
    atomicAdd(&hn[(size_t)d * DD + j], x[(size_t)s * pitch + j] * att);
}

// ---------------- layer 0 MLP: x1 = lrelu((x0+h)W1^T+b1)+lrelu((x0*h)W2^T+b2)
// Also copies x0 into out[:, 0:64]. Writes x1 to out[:, 64:128].
__global__ void k_mlp0(const float* __restrict__ x0,
                       const float* __restrict__ W1, const float* __restrict__ b1,
                       const float* __restrict__ W2, const float* __restrict__ b2,
                       float* __restrict__ out) {
    __shared__ float W1t[DD][68], W2t[DD][68];
    __shared__ float sa[16][DD], sm_[16][DD];
    const int tid = threadIdx.x;

    for (int idx = tid; idx < DD * DD; idx += 256) {
        W1t[idx >> 6][idx & 63] = W1[idx];   // W is [out_j][in_d] row-major already
        W2t[idx >> 6][idx & 63] = W2[idx];
    }
    __syncthreads();

    const int j = tid & 63, vg = tid >> 6;
    const float bb1 = b1[j], bb2 = b2[j];
    const int NTILES = N_ENT / 16;

    for (int t = blockIdx.x; t < NTILES; t += gridDim.x) {
        int n0 = t * 16;
        for (int q = tid; q < 16 * DD / 4; q += 256) {
            int v = q >> 4, c = q & 15;
            float4 xv = ((const float4*)(x0 + (size_t)(n0 + v) * DD))[c];
            float4 hv = ((const float4*)(g_hn0 + (size_t)(n0 + v) * DD))[c];
            ((float4*)sa[v])[c]  = make_float4(xv.x + hv.x, xv.y + hv.y, xv.z + hv.z, xv.w + hv.w);
            ((float4*)sm_[v])[c] = make_float4(xv.x * hv.x, xv.y * hv.y, xv.z * hv.z, xv.w * hv.w);
            ((float4*)(out + (size_t)(n0 + v) * OUTD))[c] = xv;   // copy x0 to out
        }
        __syncthreads();

        float acc_a[4] = {0.f, 0.f, 0.f, 0.f};
        float acc_m[4] = {0.f, 0.f, 0.f, 0.f};
#pragma unroll
        for (int d4 = 0; d4 < 16; d4++) {
            float4 w1 = *(const float4*)&W1t[j][d4 * 4];
            float4 w2 = *(const float4*)&W2t[j][d4 * 4];
#pragma unroll
            for (int v = 0; v < 4; v++) {
                float4 a = *(const float4*)&sa [vg * 4 + v][d4 * 4];
                float4 m = *(const float4*)&sm_[vg * 4 + v][d4 * 4];
                acc_a[v] += dot4(a, w1);
                acc_m[v] += dot4(m, w2);
            }
        }
#pragma unroll
        for (int v = 0; v < 4; v++) {
            int n = n0 + vg * 4 + v;
            out[(size_t)n * OUTD + 64 + j] = leaky(acc_a[v] + bb1) + leaky(acc_m[v] + bb2);
        }
        __syncthreads();
    }
}

// ---------------- layer 1 MLP (out dim 32): reads x1 from out[:,64:128] -----
__global__ void k_mlp1(const float* __restrict__ W1, const float* __restrict__ b1,
                       const float* __restrict__ W2, const float* __restrict__ b2,
                       float* __restrict__ out) {
    __shared__ float W1t[32][68], W2t[32][68];
    __shared__ float sa[16][DD], sm_[16][DD];
    const int tid = threadIdx.x;

    for (int idx = tid; idx < 32 * DD; idx += 256) {
        W1t[idx >> 6][idx & 63] = W1[idx];
        W2t[idx >> 6][idx & 63] = W2[idx];
    }
    __syncthreads();

    const int j = tid & 31, vg = tid >> 5;   // 8 vgroups x 2 nodes
    const float bb1 = b1[j], bb2 = b2[j];
    const int NTILES = N_ENT / 16;

    for (int t = blockIdx.x; t < NTILES; t += gridDim.x) {
        int n0 = t * 16;
        for (int q = tid; q < 16 * DD / 4; q += 256) {
            int v = q >> 4, c = q & 15;
            float4 xv = ((const float4*)(out + (size_t)(n0 + v) * OUTD + 64))[c];
            float4 hv = ((const float4*)(g_hn1 + (size_t)(n0 + v) * DD))[c];
            ((float4*)sa[v])[c]  = make_float4(xv.x + hv.x, xv.y + hv.y, xv.z + hv.z, xv.w + hv.w);
            ((float4*)sm_[v])[c] = make_float4(xv.x * hv.x, xv.y * hv.y, xv.z * hv.z, xv.w * hv.w);
        }
        __syncthreads();

        float acc_a[2] = {0.f, 0.f};
        float acc_m[2] = {0.f, 0.f};
#pragma unroll
        for (int d4 = 0; d4 < 16; d4++) {
            float4 w1 = *(const float4*)&W1t[j][d4 * 4];
            float4 w2 = *(const float4*)&W2t[j][d4 * 4];
#pragma unroll
            for (int v = 0; v < 2; v++) {
                float4 a = *(const float4*)&sa [vg * 2 + v][d4 * 4];
                float4 m = *(const float4*)&sm_[vg * 2 + v][d4 * 4];
                acc_a[v] += dot4(a, w1);
                acc_m[v] += dot4(m, w2);
            }
        }
#pragma unroll
        for (int v = 0; v < 2; v++) {
            int n = n0 + vg * 2 + v;
            out[(size_t)n * OUTD + 128 + j] = leaky(acc_a[v] + bb1) + leaky(acc_m[v] + bb2);
        }
        __syncthreads();
    }
}

// ---------------- launch ----------------
extern "C" void kernel_launch(void* const* d_in, const int* in_sizes, int n_in,
                              void* d_out, int out_size) {
    const float* entity_emb = (const float*)d_in[0];
    const float* rel_emb    = (const float*)d_in[1];
    const float* W_r        = (const float*)d_in[2];
    const float* W1_0_w     = (const float*)d_in[3];
    const float* W1_0_b     = (const float*)d_in[4];
    const float* W2_0_w     = (const float*)d_in[5];
    const float* W2_0_b     = (const float*)d_in[6];
    const float* W1_1_w     = (const float*)d_in[7];
    const float* W1_1_b     = (const float*)d_in[8];
    const float* W2_1_w     = (const float*)d_in[9];
    const float* W2_1_b     = (const float*)d_in[10];
    const int*   src        = (const int*)d_in[11];
    const int*   dst        = (const int*)d_in[12];
    const int*   et         = (const int*)d_in[13];
    float* out = (float*)d_out;

    // init scratch
    k_init<<<(N_ENT * DD + 255) / 256, 256>>>();

    // proj[n,r,:] for all nodes x relations
    k_proj<<<dim3(256, N_REL), 256>>>(entity_emb, W_r);

    // attention: logits + segment max (fused), then exp + segment sum
    k_logits<<<NE / 8, 256>>>(rel_emb, src, dst, et);
    k_exp<<<(NE + 255) / 256, 256>>>(dst);

    // layer 0: scatter h_n, then MLP (writes out[:,0:64] and out[:,64:128])
    k_scatter<<<NE / 4, 256>>>(entity_emb, DD, 0, src, dst);
    k_mlp0<<<1250, 256>>>(entity_emb, W1_0_w, W1_0_b, W2_0_w, W2_0_b, out);

    // layer 1: scatter h_n over x1 (= out[:,64:128], pitch 160), then MLP
    k_scatter<<<NE / 4, 256>>>(out + 64, OUTD, 1, src, dst);
    k_mlp1<<<1250, 256>>>(W1_1_w, W1_1_b, W2_1_w, W2_1_b, out);
}

// round 3
// speedup vs baseline: 1.8442x; 1.8442x over previous
#include <cuda_runtime.h>
#include <math.h>

#define N_ENT 100000
#define N_REL 12
#define DD 64
#define NE 1000000
#define OUTD 160   // 64 + 64 + 32
#define NSCAN ((N_ENT + 1023) / 1024)   // 98

// ---------------- device scratch (no allocations allowed) ----------------
__device__ float g_proj[(size_t)N_ENT * N_REL * DD];   // 307.2 MB
__device__ float g_logits[NE];
__device__ float g_attp[NE];          // att in CSR (dst-sorted) order
__device__ int   g_cnt[N_ENT];
__device__ int   g_off[N_ENT + 1];
__device__ int   g_cursor[N_ENT];
__device__ int   g_eidx[NE];          // CSR: edge id per sorted slot
__device__ int   g_srcp[NE];          // CSR: src per sorted slot
__device__ int   g_bsum[NSCAN];
__device__ float g_hn0[(size_t)N_ENT * DD];
__device__ float g_hn1[(size_t)N_ENT * DD];

// ---------------- helpers ----------------
__device__ __forceinline__ void fma4(float4& a, float s, float4 w) {
    a.x += s * w.x; a.y += s * w.y; a.z += s * w.z; a.w += s * w.w;
}
__device__ __forceinline__ float leaky(float x) {
    return x > 0.0f ? x : 0.01f * x;
}

// ---------------- CSR build ----------------
__global__ void k_init() {
    int i = blockIdx.x * blockDim.x + threadIdx.x;
    if (i < N_ENT) g_cnt[i] = 0;
}

__global__ void k_hist(const int* __restrict__ dst) {
    int e = blockIdx.x * 256 + threadIdx.x;
    if (e < NE) atomicAdd(&g_cnt[dst[e]], 1);
}

__global__ void k_scan1() {
    __shared__ int s[1024];
    int i = blockIdx.x * 1024 + threadIdx.x;
    int v = (i < N_ENT) ? g_cnt[i] : 0;
    s[threadIdx.x] = v;
    __syncthreads();
    for (int off = 1; off < 1024; off <<= 1) {
        int t = (threadIdx.x >= off) ? s[threadIdx.x - off] : 0;
        __syncthreads();
        s[threadIdx.x] += t;
        __syncthreads();
    }
    if (i < N_ENT) g_off[i] = s[threadIdx.x] - v;   // exclusive within block
    if (threadIdx.x == 1023) g_bsum[blockIdx.x] = s[1023];
}

__global__ void k_scan2() {
    if (threadIdx.x == 0) {
        int run = 0;
        for (int b = 0; b < NSCAN; b++) { int t = g_bsum[b]; g_bsum[b] = run; run += t; }
    }
}

__global__ void k_scan3() {
    int i = blockIdx.x * 256 + threadIdx.x;
    if (i < N_ENT) {
        int o = g_off[i] + g_bsum[i >> 10];
        g_off[i] = o;
        g_cursor[i] = o;
    }
    if (i == 0) g_off[N_ENT] = NE;
}

__global__ void k_fill(const int* __restrict__ src, const int* __restrict__ dst) {
    int e = blockIdx.x * 256 + threadIdx.x;
    if (e < NE) {
        int pos = atomicAdd(&g_cursor[dst[e]], 1);
        g_eidx[pos] = e;
        g_srcp[pos] = src[e];
    }
}

// ---------------- proj[n,r,:] = emb[n,:] @ W_r[r,:,:] ----------------
// tile: 64 nodes x 64 j; thread = 4 nodes x 4 j. Ws stored d-major: Ws[d][j].
__global__ void k_proj(const float* __restrict__ emb, const float* __restrict__ Wr) {
    __shared__ float Ws[DD][68];     // Ws[d][j]
    __shared__ float es[64][68];     // es[v][d]
    const int r = blockIdx.y;
    const int tid = threadIdx.x;

    for (int idx = tid; idx < DD * DD; idx += 256) {
        int d = idx >> 6, j = idx & 63;
        Ws[d][j] = Wr[(size_t)r * DD * DD + idx];   // W_r[r][d][j]
    }
    __syncthreads();

    const int jg = tid & 15, vg = tid >> 4;
    const int j0 = jg * 4;
    const int NT = (N_ENT + 63) / 64;   // 1563

    for (int t = blockIdx.x; t < NT; t += gridDim.x) {
        int n0 = t * 64;
        for (int q = tid; q < 64 * 16; q += 256) {
            int v = q >> 4, c = q & 15;
            float4 val = make_float4(0.f, 0.f, 0.f, 0.f);
            if (n0 + v < N_ENT) val = ((const float4*)(emb + (size_t)(n0 + v) * DD))[c];
            *(float4*)&es[v][c * 4] = val;
        }
        __syncthreads();

        float4 acc[4] = {};   // acc[vv] spans j0..j0+3
#pragma unroll
        for (int d4 = 0; d4 < 16; d4++) {
            float4 e0 = *(const float4*)&es[vg * 4 + 0][d4 * 4];
            float4 e1 = *(const float4*)&es[vg * 4 + 1][d4 * 4];
            float4 e2 = *(const float4*)&es[vg * 4 + 2][d4 * 4];
            float4 e3 = *(const float4*)&es[vg * 4 + 3][d4 * 4];
#pragma unroll
            for (int dd = 0; dd < 4; dd++) {
                float4 w = *(const float4*)&Ws[d4 * 4 + dd][j0];
                float s0 = dd == 0 ? e0.x : dd == 1 ? e0.y : dd == 2 ? e0.z : e0.w;
                float s1 = dd == 0 ? e1.x : dd == 1 ? e1.y : dd == 2 ? e1.z : e1.w;
                float s2 = dd == 0 ? e2.x : dd == 1 ? e2.y : dd == 2 ? e2.z : e2.w;
                float s3 = dd == 0 ? e3.x : dd == 1 ? e3.y : dd == 2 ? e3.z : e3.w;
                fma4(acc[0], s0, w);
                fma4(acc[1], s1, w);
                fma4(acc[2], s2, w);
                fma4(acc[3], s3, w);
            }
        }
#pragma unroll
        for (int vv = 0; vv < 4; vv++) {
            int n = n0 + vg * 4 + vv;
            if (n < N_ENT)
                *(float4*)&g_proj[((size_t)n * N_REL + r) * DD + j0] = acc[vv];
        }
        __syncthreads();
    }
}

// ---------------- per-edge logits (no atomics) ----------------
__global__ void k_logits(const float* __restrict__ rel_emb,
                         const int* __restrict__ src, const int* __restrict__ dst,
                         const int* __restrict__ et) {
    int e = blockIdx.x * 8 + (threadIdx.x >> 5);
    if (e >= NE) return;
    int l = threadIdx.x & 31;
    int s = src[e], d = dst[e], r = et[e];
    const float* pt = g_proj + ((size_t)s * N_REL + r) * DD;
    const float* ph = g_proj + ((size_t)d * N_REL + r) * DD;
    const float* pr = rel_emb + (size_t)r * DD;

    float sum = pt[l]      * tanhf(ph[l]      + pr[l])
              + pt[l + 32] * tanhf(ph[l + 32] + pr[l + 32]);
#pragma unroll
    for (int o = 16; o; o >>= 1) sum += __shfl_xor_sync(0xffffffffu, sum, o);
    if (l == 0) g_logits[e] = sum;
}

// ---------------- per-dst softmax via CSR (warp per node) ----------------
__global__ void k_att() {
    int n = blockIdx.x * 8 + (threadIdx.x >> 5);
    if (n >= N_ENT) return;
    int l = threadIdx.x & 31;
    int beg = g_off[n], end = g_off[n + 1];
    if (beg == end) return;

    float mx = -INFINITY;
    for (int p = beg + l; p < end; p += 32) mx = fmaxf(mx, g_logits[g_eidx[p]]);
#pragma unroll
    for (int o = 16; o; o >>= 1) mx = fmaxf(mx, __shfl_xor_sync(0xffffffffu, mx, o));

    float s = 0.f;
    for (int p = beg + l; p < end; p += 32) s += expf(g_logits[g_eidx[p]] - mx);
#pragma unroll
    for (int o = 16; o; o >>= 1) s += __shfl_xor_sync(0xffffffffu, s, o);
    float inv = 1.0f / s;

    for (int p = beg + l; p < end; p += 32)
        g_attp[p] = expf(g_logits[g_eidx[p]] - mx) * inv;
}

// ---------------- h_n[n] = sum over in-edges att * x[src] (no atomics) ----
// which: 0 -> x = entity_emb (pitch 64) into g_hn0; 1 -> x = x1 (out+64, pitch 160) into g_hn1.
// NOTE: device globals are selected INSIDE the kernel (never passed from host).
__global__ void k_gather(const float* __restrict__ xbase, int pitch, int which) {
    int n = blockIdx.x * 8 + (threadIdx.x >> 5);
    if (n >= N_ENT) return;
    int l = threadIdx.x & 31;
    float* hn = which ? g_hn1 : g_hn0;
    int beg = g_off[n], end = g_off[n + 1];
    float a0 = 0.f, a1 = 0.f;
    for (int p = beg; p < end; p++) {
        float att = g_attp[p];
        const float* xs = xbase + (size_t)g_srcp[p] * pitch;
        a0 += att * xs[l];
        a1 += att * xs[l + 32];
    }
    hn[(size_t)n * DD + l]      = a0;
    hn[(size_t)n * DD + l + 32] = a1;
}

// ---------------- layer 0 MLP (dynamic smem) ----------------
// tile 64 nodes x 64 j; thread = 4 nodes x 4 j, two matmuls.
__global__ void k_mlp0(const float* __restrict__ x0,
                       const float* __restrict__ W1, const float* __restrict__ b1,
                       const float* __restrict__ W2, const float* __restrict__ b2,
                       float* __restrict__ out) {
    extern __shared__ float dsm[];
    float* W1s = dsm;                 // [64][68] d-major
    float* W2s = dsm + 64 * 68;
    float* sa  = dsm + 2 * 64 * 68;   // [64][68]
    float* sm_ = dsm + 3 * 64 * 68;
    const int tid = threadIdx.x;

    for (int idx = tid; idx < DD * DD; idx += 256) {
        int j = idx >> 6, d = idx & 63;     // W[j][d] row-major
        W1s[d * 68 + j] = W1[idx];
        W2s[d * 68 + j] = W2[idx];
    }
    __syncthreads();

    const int jg = tid & 15, vg = tid >> 4;
    const int j0 = jg * 4;
    const float4 b1v = *(const float4*)&b1[j0];
    const float4 b2v = *(const float4*)&b2[j0];
    const int NT = (N_ENT + 63) / 64;

    for (int t = blockIdx.x; t < NT; t += gridDim.x) {
        int n0 = t * 64;
        for (int q = tid; q < 64 * 16; q += 256) {
            int v = q >> 4, c = q & 15;
            int n = n0 + v;
            float4 xv = make_float4(0.f, 0.f, 0.f, 0.f), hv = xv;
            if (n < N_ENT) {
                xv = ((const float4*)(x0 + (size_t)n * DD))[c];
                hv = ((const float4*)(g_hn0 + (size_t)n * DD))[c];
                ((float4*)(out + (size_t)n * OUTD))[c] = xv;   // out[:,0:64] = x0
            }
            *(float4*)&sa [v * 68 + c * 4] = make_float4(xv.x + hv.x, xv.y + hv.y, xv.z + hv.z, xv.w + hv.w);
            *(float4*)&sm_[v * 68 + c * 4] = make_float4(xv.x * hv.x, xv.y * hv.y, xv.z * hv.z, xv.w * hv.w);
        }
        __syncthreads();

        float4 acc_a[4] = {}, acc_m[4] = {};
#pragma unroll
        for (int d4 = 0; d4 < 16; d4++) {
            float4 ea[4], em[4];
#pragma unroll
            for (int vv = 0; vv < 4; vv++) {
                ea[vv] = *(const float4*)&sa [(vg * 4 + vv) * 68 + d4 * 4];
                em[vv] = *(const float4*)&sm_[(vg * 4 + vv) * 68 + d4 * 4];
            }
#pragma unroll
            for (int dd = 0; dd < 4; dd++) {
                float4 w1 = *(const float4*)&W1s[(d4 * 4 + dd) * 68 + j0];
                float4 w2 = *(const float4*)&W2s[(d4 * 4 + dd) * 68 + j0];
#pragma unroll
                for (int vv = 0; vv < 4; vv++) {
                    float sA = dd == 0 ? ea[vv].x : dd == 1 ? ea[vv].y : dd == 2 ? ea[vv].z : ea[vv].w;
                    float sM = dd == 0 ? em[vv].x : dd == 1 ? em[vv].y : dd == 2 ? em[vv].z : em[vv].w;
                    fma4(acc_a[vv], sA, w1);
                    fma4(acc_m[vv], sM, w2);
                }
            }
        }
#pragma unroll
        for (int vv = 0; vv < 4; vv++) {
            int n = n0 + vg * 4 + vv;
            if (n < N_ENT) {
                float4 r;
                r.x = leaky(acc_a[vv].x + b1v.x) + leaky(acc_m[vv].x + b2v.x);
                r.y = leaky(acc_a[vv].y + b1v.y) + leaky(acc_m[vv].y + b2v.y);
                r.z = leaky(acc_a[vv].z + b1v.z) + leaky(acc_m[vv].z + b2v.z);
                r.w = leaky(acc_a[vv].w + b1v.w) + leaky(acc_m[vv].w + b2v.w);
                *(float4*)&out[(size_t)n * OUTD + 64 + j0] = r;
            }
        }
        __syncthreads();
    }
}

// ---------------- layer 1 MLP (out dim 32, dynamic smem) ----------------
// tile 64 nodes x 32 j; thread = 2 nodes x 4 j, two matmuls.
__global__ void k_mlp1(const float* __restrict__ W1, const float* __restrict__ b1,
                       const float* __restrict__ W2, const float* __restrict__ b2,
                       float* __restrict__ out) {
    extern __shared__ float dsm[];
    float* W1s = dsm;                  // [64][36] d-major
    float* W2s = dsm + 64 * 36;
    float* sa  = dsm + 2 * 64 * 36;    // [64][68]
    float* sm_ = dsm + 2 * 64 * 36 + 64 * 68;
    const int tid = threadIdx.x;

    for (int idx = tid; idx < 32 * DD; idx += 256) {
        int j = idx >> 6, d = idx & 63;   // W[j][d], j<32
        W1s[d * 36 + j] = W1[idx];
        W2s[d * 36 + j] = W2[idx];
    }
    __syncthreads();

    const int jg = tid & 7, vgp = tid >> 3;   // 8 j-groups, 32 v-groups (2 nodes each)
    const int j0 = jg * 4;
    const float4 b1v = *(const float4*)&b1[j0];
    const float4 b2v = *(const float4*)&b2[j0];
    const int NT = (N_ENT + 63) / 64;

    for (int t = blockIdx.x; t < NT; t += gridDim.x) {
        int n0 = t * 64;
        for (int q = tid; q < 64 * 16; q += 256) {
            int v = q >> 4, c = q & 15;
            int n = n0 + v;
            float4 xv = make_float4(0.f, 0.f, 0.f, 0.f), hv = xv;
            if (n < N_ENT) {
                xv = ((const float4*)(out + (size_t)n * OUTD + 64))[c];
                hv = ((const float4*)(g_hn1 + (size_t)n * DD))[c];
            }
            *(float4*)&sa [v * 68 + c * 4] = make_float4(xv.x + hv.x, xv.y + hv.y, xv.z + hv.z, xv.w + hv.w);
            *(float4*)&sm_[v * 68 + c * 4] = make_float4(xv.x * hv.x, xv.y * hv.y, xv.z * hv.z, xv.w * hv.w);
        }
        __syncthreads();

        float4 acc_a[2] = {}, acc_m[2] = {};
#pragma unroll
        for (int d4 = 0; d4 < 16; d4++) {
            float4 ea[2], em[2];
#pragma unroll
            for (int vv = 0; vv < 2; vv++) {
                ea[vv] = *(const float4*)&sa [(vgp * 2 + vv) * 68 + d4 * 4];
                em[vv] = *(const float4*)&sm_[(vgp * 2 + vv) * 68 + d4 * 4];
            }
#pragma unroll
            for (int dd = 0; dd < 4; dd++) {
                float4 w1 = *(const float4*)&W1s[(d4 * 4 + dd) * 36 + j0];
                float4 w2 = *(const float4*)&W2s[(d4 * 4 + dd) * 36 + j0];
#pragma unroll
                for (int vv = 0; vv < 2; vv++) {
                    float sA = dd == 0 ? ea[vv].x : dd == 1 ? ea[vv].y : dd == 2 ? ea[vv].z : ea[vv].w;
                    float sM = dd == 0 ? em[vv].x : dd == 1 ? em[vv].y : dd == 2 ? em[vv].z : em[vv].w;
                    fma4(acc_a[vv], sA, w1);
                    fma4(acc_m[vv], sM, w2);
                }
            }
        }
#pragma unroll
        for (int vv = 0; vv < 2; vv++) {
            int n = n0 + vgp * 2 + vv;
            if (n < N_ENT) {
                float4 r;
                r.x = leaky(acc_a[vv].x + b1v.x) + leaky(acc_m[vv].x + b2v.x);
                r.y = leaky(acc_a[vv].y + b1v.y) + leaky(acc_m[vv].y + b2v.y);
                r.z = leaky(acc_a[vv].z + b1v.z) + leaky(acc_m[vv].z + b2v.z);
                r.w = leaky(acc_a[vv].w + b1v.w) + leaky(acc_m[vv].w + b2v.w);
                *(float4*)&out[(size_t)n * OUTD + 128 + j0] = r;
            }
        }
        __syncthreads();
    }
}

// ---------------- launch ----------------
extern "C" void kernel_launch(void* const* d_in, const int* in_sizes, int n_in,
                              void* d_out, int out_size) {
    const float* entity_emb = (const float*)d_in[0];
    const float* rel_emb    = (const float*)d_in[1];
    const float* W_r        = (const float*)d_in[2];
    const float* W1_0_w     = (const float*)d_in[3];
    const float* W1_0_b     = (const float*)d_in[4];
    const float* W2_0_w     = (const float*)d_in[5];
    const float* W2_0_b     = (const float*)d_in[6];
    const float* W1_1_w     = (const float*)d_in[7];
    const float* W1_1_b     = (const float*)d_in[8];
    const float* W2_1_w     = (const float*)d_in[9];
    const float* W2_1_b     = (const float*)d_in[10];
    const int*   src        = (const int*)d_in[11];
    const int*   dst        = (const int*)d_in[12];
    const int*   et         = (const int*)d_in[13];
    float* out = (float*)d_out;

    const int SM_MLP0 = 4 * 64 * 68 * 4;                 // 69632 B
    const int SM_MLP1 = (2 * 64 * 36 + 2 * 64 * 68) * 4; // 53248 B
    cudaFuncSetAttribute(k_mlp0, cudaFuncAttributeMaxDynamicSharedMemorySize, SM_MLP0);
    cudaFuncSetAttribute(k_mlp1, cudaFuncAttributeMaxDynamicSharedMemorySize, SM_MLP1);

    // CSR build (counting sort by dst)
    k_init<<<(N_ENT + 255) / 256, 256>>>();
    k_hist<<<(NE + 255) / 256, 256>>>(dst);
    k_scan1<<<NSCAN, 1024>>>();
    k_scan2<<<1, 32>>>();
    k_scan3<<<(N_ENT + 255) / 256, 256>>>();
    k_fill<<<(NE + 255) / 256, 256>>>(src, dst);

    // proj + attention
    k_proj<<<dim3(256, N_REL), 256>>>(entity_emb, W_r);
    k_logits<<<NE / 8, 256>>>(rel_emb, src, dst, et);
    k_att<<<(N_ENT + 7) / 8, 256>>>();

    // layer 0
    k_gather<<<(N_ENT + 7) / 8, 256>>>(entity_emb, DD, 0);
    k_mlp0<<<512, 256, SM_MLP0>>>(entity_emb, W1_0_w, W1_0_b, W2_0_w, W2_0_b, out);

    // layer 1
    k_gather<<<(N_ENT + 7) / 8, 256>>>(out + 64, OUTD, 1);
    k_mlp1<<<512, 256, SM_MLP1>>>(W1_1_w, W1_1_b, W2_1_w, W2_1_b, out);
}

// round 5
// speedup vs baseline: 2.3852x; 1.2934x over previous
#include <cuda_runtime.h>
#include <math.h>
#include <stdint.h>

#define N_ENT 100000
#define N_REL 12
#define DD 64
#define NE 1000000
#define OUTD 160   // 64 + 64 + 32
#define NSCAN ((N_ENT + 1023) / 1024)   // 98
#define TILE_M 128
#define NTILES_M ((N_ENT + TILE_M - 1) / TILE_M)   // 782

// ---------------- device scratch (no allocations allowed) ----------------
__device__ float g_proj[(size_t)N_ENT * N_REL * DD];   // 307.2 MB
__device__ float g_Wt[N_REL * DD * DD];                // W^T, tf32-rounded: [r][j][d]
__device__ float g_logits[NE];        // logits in CSR (dst-sorted) order
__device__ float g_attp[NE];          // att in CSR order
__device__ int   g_cnt[N_ENT];
__device__ int   g_off[N_ENT + 1];
__device__ int   g_cursor[N_ENT];
__device__ int   g_einv[NE];          // edge id -> CSR slot
__device__ int   g_srcp[NE];          // CSR: src per sorted slot
__device__ int   g_bsum[NSCAN];
__device__ float g_hn0[(size_t)N_ENT * DD];
__device__ float g_hn1[(size_t)N_ENT * DD];

// ---------------- helpers ----------------
__device__ __forceinline__ float leaky(float x) { return x > 0.0f ? x : 0.01f * x; }
__device__ __forceinline__ void fma4(float4& a, float s, float4 w) {
    a.x += s * w.x; a.y += s * w.y; a.z += s * w.z; a.w += s * w.w;
}
__device__ __forceinline__ float to_tf32(float v) {
    float r;
    asm("cvt.rna.tf32.f32 %0, %1;" : "=f"(r) : "f"(v));
    return r;
}
// m16n8k8 row.col tf32 MMA, fp32 accumulate (portable PTX, no 'a' feature)
__device__ __forceinline__ void mma_tf32(float c[4], uint32_t a0, uint32_t a1,
                                         uint32_t a2, uint32_t a3,
                                         uint32_t b0, uint32_t b1) {
    asm volatile(
        "mma.sync.aligned.m16n8k8.row.col.f32.tf32.tf32.f32 "
        "{%0,%1,%2,%3}, {%4,%5,%6,%7}, {%8,%9}, {%0,%1,%2,%3};"
        : "+f"(c[0]), "+f"(c[1]), "+f"(c[2]), "+f"(c[3])
        : "r"(a0), "r"(a1), "r"(a2), "r"(a3), "r"(b0), "r"(b1));
}

// ---------------- CSR build ----------------
__global__ void k_init() {
    int i = blockIdx.x * blockDim.x + threadIdx.x;
    if (i < N_ENT) g_cnt[i] = 0;
}

__global__ void k_hist(const int* __restrict__ dst) {
    int e = blockIdx.x * 256 + threadIdx.x;
    if (e < NE) atomicAdd(&g_cnt[dst[e]], 1);
}

__global__ void k_scan1() {
    __shared__ int s[1024];
    int i = blockIdx.x * 1024 + threadIdx.x;
    int v = (i < N_ENT) ? g_cnt[i] : 0;
    s[threadIdx.x] = v;
    __syncthreads();
    for (int off = 1; off < 1024; off <<= 1) {
        int t = (threadIdx.x >= off) ? s[threadIdx.x - off] : 0;
        __syncthreads();
        s[threadIdx.x] += t;
        __syncthreads();
    }
    if (i < N_ENT) g_off[i] = s[threadIdx.x] - v;
    if (threadIdx.x == 1023) g_bsum[blockIdx.x] = s[1023];
}

__global__ void k_scan2() {
    __shared__ int s[128];
    int t = threadIdx.x;
    int v0 = (t < NSCAN) ? g_bsum[t] : 0;
    s[t] = v0;
    __syncthreads();
    for (int off = 1; off < 128; off <<= 1) {
        int v = (t >= off) ? s[t - off] : 0;
        __syncthreads();
        s[t] += v;
        __syncthreads();
    }
    if (t < NSCAN) g_bsum[t] = s[t] - v0;   // exclusive
}

__global__ void k_scan3() {
    int i = blockIdx.x * 256 + threadIdx.x;
    if (i < N_ENT) {
        int o = g_off[i] + g_bsum[i >> 10];
        g_off[i] = o;
        g_cursor[i] = o;
    }
    if (i == 0) g_off[N_ENT] = NE;
}

__global__ void k_fill(const int* __restrict__ src, const int* __restrict__ dst) {
    int e = blockIdx.x * 256 + threadIdx.x;
    if (e < NE) {
        int pos = atomicAdd(&g_cursor[dst[e]], 1);
        g_einv[e] = pos;
        g_srcp[pos] = src[e];
    }
}

// ---------------- W prep: g_Wt[r][j][d] = tf32(W_r[r][d][j]) ----------------
__global__ void k_prepW(const float* __restrict__ Wr) {
    int idx = blockIdx.x * 256 + threadIdx.x;
    if (idx >= N_REL * DD * DD) return;
    int r = idx >> 12;
    int e = idx & 4095;
    int d = e >> 6, j = e & 63;         // source element W[r][d][j]
    g_Wt[r * 4096 + j * DD + d] = to_tf32(Wr[idx]);
}

// ---------------- tf32 mma.sync proj: one 128-node tile per CTA, all 12 r --
// 256 threads = 8 warps; warp w computes rows [w*16, w*16+16) x 64 cols.
// smem: A[128][68] (tf32 bits), Wt_s[64][68] (tf32 bits, [j][d])
__global__ void k_projmma(const float* __restrict__ emb) {
    extern __shared__ float smA[];           // [128][68]
    float* smW = smA + 128 * 68;             // [64][68]
    const int tid = threadIdx.x;
    const int wid = tid >> 5, lane = tid & 31;
    const int g = lane >> 2, t4 = lane & 3;  // mma fragment coords
    const int n0 = blockIdx.x * TILE_M;

    // stage A tile (rows zero-filled OOB), rounding to tf32
    for (int idx = tid; idx < TILE_M * 16; idx += 256) {
        int m = idx >> 4, c = idx & 15;
        float4 v = make_float4(0.f, 0.f, 0.f, 0.f);
        if (n0 + m < N_ENT) v = ((const float4*)(emb + (size_t)(n0 + m) * DD))[c];
        v.x = to_tf32(v.x); v.y = to_tf32(v.y); v.z = to_tf32(v.z); v.w = to_tf32(v.w);
        *(float4*)&smA[m * 68 + c * 4] = v;
    }
    __syncthreads();

    const int mb = wid * 16;                 // warp's row base within tile
    const int row0 = n0 + mb + g;            // global row for c[.][0..1]
    const int row1 = row0 + 8;               // global row for c[.][2..3]

    for (int r = 0; r < N_REL; r++) {
        // copy W^T_r (16KB, L2-resident, already tf32-rounded)
        for (int q = tid; q < 64 * 16; q += 256) {
            int row = q >> 4, c = q & 15;
            *(float4*)&smW[row * 68 + c * 4] =
                ((const float4*)(g_Wt + r * 4096 + row * 64))[c];
        }
        __syncthreads();

        float acc[8][4];
#pragma unroll
        for (int nt = 0; nt < 8; nt++)
#pragma unroll
            for (int q = 0; q < 4; q++) acc[nt][q] = 0.f;

#pragma unroll
        for (int ks = 0; ks < 8; ks++) {
            int k0 = ks * 8;
            uint32_t a0 = __float_as_uint(smA[(mb + g)     * 68 + k0 + t4]);
            uint32_t a1 = __float_as_uint(smA[(mb + g + 8) * 68 + k0 + t4]);
            uint32_t a2 = __float_as_uint(smA[(mb + g)     * 68 + k0 + t4 + 4]);
            uint32_t a3 = __float_as_uint(smA[(mb + g + 8) * 68 + k0 + t4 + 4]);
#pragma unroll
            for (int nt = 0; nt < 8; nt++) {
                // B[k][n] with n = nt*8+g, k = k0+t4 (+4); smW is [j=n][d=k]
                uint32_t b0 = __float_as_uint(smW[(nt * 8 + g) * 68 + k0 + t4]);
                uint32_t b1 = __float_as_uint(smW[(nt * 8 + g) * 68 + k0 + t4 + 4]);
                mma_tf32(acc[nt], a0, a1, a2, a3, b0, b1);
            }
        }

        // epilogue: c0,c1 -> [row0][j..j+1], c2,c3 -> [row1][j..j+1]
        if (row0 < N_ENT) {
            float* base = g_proj + ((size_t)row0 * N_REL + r) * DD;
#pragma unroll
            for (int nt = 0; nt < 8; nt++)
                *(float2*)&base[nt * 8 + t4 * 2] = make_float2(acc[nt][0], acc[nt][1]);
        }
        if (row1 < N_ENT) {
            float* base = g_proj + ((size_t)row1 * N_REL + r) * DD;
#pragma unroll
            for (int nt = 0; nt < 8; nt++)
                *(float2*)&base[nt * 8 + t4 * 2] = make_float2(acc[nt][2], acc[nt][3]);
        }
        __syncthreads();   // all reads of smW done before next overwrite
    }
}

// ---------------- per-edge logits, scattered to CSR order ----------------
__global__ void k_logits(const float* __restrict__ rel_emb,
                         const int* __restrict__ src, const int* __restrict__ dst,
                         const int* __restrict__ et) {
    int e = blockIdx.x * 8 + (threadIdx.x >> 5);
    if (e >= NE) return;
    int l = threadIdx.x & 31;
    int s = src[e], d = dst[e], r = et[e];
    const float* pt = g_proj + ((size_t)s * N_REL + r) * DD;
    const float* ph = g_proj + ((size_t)d * N_REL + r) * DD;
    const float* pr = rel_emb + (size_t)r * DD;

    float sum = pt[l]      * tanhf(ph[l]      + pr[l])
              + pt[l + 32] * tanhf(ph[l + 32] + pr[l + 32]);
#pragma unroll
    for (int o = 16; o; o >>= 1) sum += __shfl_xor_sync(0xffffffffu, sum, o);
    if (l == 0) g_logits[g_einv[e]] = sum;
}

// ---------------- per-dst softmax via CSR (contiguous; warp per node) -----
__global__ void k_att() {
    int n = blockIdx.x * 8 + (threadIdx.x >> 5);
    if (n >= N_ENT) return;
    int l = threadIdx.x & 31;
    int beg = g_off[n], end = g_off[n + 1];
    if (beg == end) return;

    float mx = -INFINITY;
    for (int p = beg + l; p < end; p += 32) mx = fmaxf(mx, g_logits[p]);
#pragma unroll
    for (int o = 16; o; o >>= 1) mx = fmaxf(mx, __shfl_xor_sync(0xffffffffu, mx, o));

    float s = 0.f;
    for (int p = beg + l; p < end; p += 32) s += expf(g_logits[p] - mx);
#pragma unroll
    for (int o = 16; o; o >>= 1) s += __shfl_xor_sync(0xffffffffu, s, o);
    float inv = 1.0f / s;

    for (int p = beg + l; p < end; p += 32)
        g_attp[p] = expf(g_logits[p] - mx) * inv;
}

// ---------------- h_n[n] = sum over in-edges att * x[src] (no atomics) ----
__global__ void k_gather(const float* __restrict__ xbase, int pitch, int which) {
    int n = blockIdx.x * 8 + (threadIdx.x >> 5);
    if (n >= N_ENT) return;
    int l = threadIdx.x & 31;
    float* hn = which ? g_hn1 : g_hn0;
    int beg = g_off[n], end = g_off[n + 1];
    float a0 = 0.f, a1 = 0.f;
    for (int p = beg; p < end; p++) {
        float att = g_attp[p];
        const float* xs = xbase + (size_t)g_srcp[p] * pitch;
        a0 += att * xs[l];
        a1 += att * xs[l + 32];
    }
    hn[(size_t)n * DD + l]      = a0;
    hn[(size_t)n * DD + l + 32] = a1;
}

// ---------------- layer 0 MLP ----------------
__global__ void k_mlp0(const float* __restrict__ x0,
                       const float* __restrict__ W1, const float* __restrict__ b1,
                       const float* __restrict__ W2, const float* __restrict__ b2,
                       float* __restrict__ out) {
    extern __shared__ float dsm[];
    float* W1s = dsm;
    float* W2s = dsm + 64 * 68;
    float* sa  = dsm + 2 * 64 * 68;
    float* sm_ = dsm + 3 * 64 * 68;
    const int tid = threadIdx.x;

    for (int idx = tid; idx < DD * DD; idx += 256) {
        int j = idx >> 6, d = idx & 63;
        W1s[d * 68 + j] = W1[idx];
        W2s[d * 68 + j] = W2[idx];
    }
    __syncthreads();

    const int jg = tid & 15, vg = tid >> 4;
    const int j0 = jg * 4;
    const float4 b1v = *(const float4*)&b1[j0];
    const float4 b2v = *(const float4*)&b2[j0];
    const int NT = (N_ENT + 63) / 64;

    for (int t = blockIdx.x; t < NT; t += gridDim.x) {
        int n0 = t * 64;
        for (int q = tid; q < 64 * 16; q += 256) {
            int v = q >> 4, c = q & 15;
            int n = n0 + v;
            float4 xv = make_float4(0.f, 0.f, 0.f, 0.f), hv = xv;
            if (n < N_ENT) {
                xv = ((const float4*)(x0 + (size_t)n * DD))[c];
                hv = ((const float4*)(g_hn0 + (size_t)n * DD))[c];
                ((float4*)(out + (size_t)n * OUTD))[c] = xv;
            }
            *(float4*)&sa [v * 68 + c * 4] = make_float4(xv.x + hv.x, xv.y + hv.y, xv.z + hv.z, xv.w + hv.w);
            *(float4*)&sm_[v * 68 + c * 4] = make_float4(xv.x * hv.x, xv.y * hv.y, xv.z * hv.z, xv.w * hv.w);
        }
        __syncthreads();

        float4 acc_a[4] = {}, acc_m[4] = {};
#pragma unroll
        for (int d4 = 0; d4 < 16; d4++) {
            float4 ea[4], em[4];
#pragma unroll
            for (int vv = 0; vv < 4; vv++) {
                ea[vv] = *(const float4*)&sa [(vg * 4 + vv) * 68 + d4 * 4];
                em[vv] = *(const float4*)&sm_[(vg * 4 + vv) * 68 + d4 * 4];
            }
#pragma unroll
            for (int dd = 0; dd < 4; dd++) {
                float4 w1 = *(const float4*)&W1s[(d4 * 4 + dd) * 68 + j0];
                float4 w2 = *(const float4*)&W2s[(d4 * 4 + dd) * 68 + j0];
#pragma unroll
                for (int vv = 0; vv < 4; vv++) {
                    float sA = dd == 0 ? ea[vv].x : dd == 1 ? ea[vv].y : dd == 2 ? ea[vv].z : ea[vv].w;
                    float sM = dd == 0 ? em[vv].x : dd == 1 ? em[vv].y : dd == 2 ? em[vv].z : em[vv].w;
                    fma4(acc_a[vv], sA, w1);
                    fma4(acc_m[vv], sM, w2);
                }
            }
        }
#pragma unroll
        for (int vv = 0; vv < 4; vv++) {
            int n = n0 + vg * 4 + vv;
            if (n < N_ENT) {
                float4 r;
                r.x = leaky(acc_a[vv].x + b1v.x) + leaky(acc_m[vv].x + b2v.x);
                r.y = leaky(acc_a[vv].y + b1v.y) + leaky(acc_m[vv].y + b2v.y);
                r.z = leaky(acc_a[vv].z + b1v.z) + leaky(acc_m[vv].z + b2v.z);
                r.w = leaky(acc_a[vv].w + b1v.w) + leaky(acc_m[vv].w + b2v.w);
                *(float4*)&out[(size_t)n * OUTD + 64 + j0] = r;
            }
        }
        __syncthreads();
    }
}

// ---------------- layer 1 MLP (out dim 32) ----------------
__global__ void k_mlp1(const float* __restrict__ W1, const float* __restrict__ b1,
                       const float* __restrict__ W2, const float* __restrict__ b2,
                       float* __restrict__ out) {
    extern __shared__ float dsm[];
    float* W1s = dsm;
    float* W2s = dsm + 64 * 36;
    float* sa  = dsm + 2 * 64 * 36;
    float* sm_ = dsm + 2 * 64 * 36 + 64 * 68;
    const int tid = threadIdx.x;

    for (int idx = tid; idx < 32 * DD; idx += 256) {
        int j = idx >> 6, d = idx & 63;
        W1s[d * 36 + j] = W1[idx];
        W2s[d * 36 + j] = W2[idx];
    }
    __syncthreads();

    const int jg = tid & 7, vgp = tid >> 3;
    const int j0 = jg * 4;
    const float4 b1v = *(const float4*)&b1[j0];
    const float4 b2v = *(const float4*)&b2[j0];
    const int NT = (N_ENT + 63) / 64;

    for (int t = blockIdx.x; t < NT; t += gridDim.x) {
        int n0 = t * 64;
        for (int q = tid; q < 64 * 16; q += 256) {
            int v = q >> 4, c = q & 15;
            int n = n0 + v;
            float4 xv = make_float4(0.f, 0.f, 0.f, 0.f), hv = xv;
            if (n < N_ENT) {
                xv = ((const float4*)(out + (size_t)n * OUTD + 64))[c];
                hv = ((const float4*)(g_hn1 + (size_t)n * DD))[c];
            }
            *(float4*)&sa [v * 68 + c * 4] = make_float4(xv.x + hv.x, xv.y + hv.y, xv.z + hv.z, xv.w + hv.w);
            *(float4*)&sm_[v * 68 + c * 4] = make_float4(xv.x * hv.x, xv.y * hv.y, xv.z * hv.z, xv.w * hv.w);
        }
        __syncthreads();

        float4 acc_a[2] = {}, acc_m[2] = {};
#pragma unroll
        for (int d4 = 0; d4 < 16; d4++) {
            float4 ea[2], em[2];
#pragma unroll
            for (int vv = 0; vv < 2; vv++) {
                ea[vv] = *(const float4*)&sa [(vgp * 2 + vv) * 68 + d4 * 4];
                em[vv] = *(const float4*)&sm_[(vgp * 2 + vv) * 68 + d4 * 4];
            }
#pragma unroll
            for (int dd = 0; dd < 4; dd++) {
                float4 w1 = *(const float4*)&W1s[(d4 * 4 + dd) * 36 + j0];
                float4 w2 = *(const float4*)&W2s[(d4 * 4 + dd) * 36 + j0];
#pragma unroll
                for (int vv = 0; vv < 2; vv++) {
                    float sA = dd == 0 ? ea[vv].x : dd == 1 ? ea[vv].y : dd == 2 ? ea[vv].z : ea[vv].w;
                    float sM = dd == 0 ? em[vv].x : dd == 1 ? em[vv].y : dd == 2 ? em[vv].z : em[vv].w;
                    fma4(acc_a[vv], sA, w1);
                    fma4(acc_m[vv], sM, w2);
                }
            }
        }
#pragma unroll
        for (int vv = 0; vv < 2; vv++) {
            int n = n0 + vgp * 2 + vv;
            if (n < N_ENT) {
                float4 r;
                r.x = leaky(acc_a[vv].x + b1v.x) + leaky(acc_m[vv].x + b2v.x);
                r.y = leaky(acc_a[vv].y + b1v.y) + leaky(acc_m[vv].y + b2v.y);
                r.z = leaky(acc_a[vv].z + b1v.z) + leaky(acc_m[vv].z + b2v.z);
                r.w = leaky(acc_a[vv].w + b1v.w) + leaky(acc_m[vv].w + b2v.w);
                *(float4*)&out[(size_t)n * OUTD + 128 + j0] = r;
            }
        }
        __syncthreads();
    }
}

// ---------------- launch ----------------
extern "C" void kernel_launch(void* const* d_in, const int* in_sizes, int n_in,
                              void* d_out, int out_size) {
    const float* entity_emb = (const float*)d_in[0];
    const float* rel_emb    = (const float*)d_in[1];
    const float* W_r        = (const float*)d_in[2];
    const float* W1_0_w     = (const float*)d_in[3];
    const float* W1_0_b     = (const float*)d_in[4];
    const float* W2_0_w     = (const float*)d_in[5];
    const float* W2_0_b     = (const float*)d_in[6];
    const float* W1_1_w     = (const float*)d_in[7];
    const float* W1_1_b     = (const float*)d_in[8];
    const float* W2_1_w     = (const float*)d_in[9];
    const float* W2_1_b     = (const float*)d_in[10];
    const int*   src        = (const int*)d_in[11];
    const int*   dst        = (const int*)d_in[12];
    const int*   et         = (const int*)d_in[13];
    float* out = (float*)d_out;

    const int SM_PROJ = (128 * 68 + 64 * 68) * 4;         // 52224 B
    const int SM_MLP0 = 4 * 64 * 68 * 4;                  // 69632 B
    const int SM_MLP1 = (2 * 64 * 36 + 2 * 64 * 68) * 4;  // 53248 B
    cudaFuncSetAttribute(k_projmma, cudaFuncAttributeMaxDynamicSharedMemorySize, SM_PROJ);
    cudaFuncSetAttribute(k_mlp0, cudaFuncAttributeMaxDynamicSharedMemorySize, SM_MLP0);
    cudaFuncSetAttribute(k_mlp1, cudaFuncAttributeMaxDynamicSharedMemorySize, SM_MLP1);

    // CSR build (counting sort by dst)
    k_init<<<(N_ENT + 255) / 256, 256>>>();
    k_hist<<<(NE + 255) / 256, 256>>>(dst);
    k_scan1<<<NSCAN, 1024>>>();
    k_scan2<<<1, 128>>>();
    k_scan3<<<(N_ENT + 255) / 256, 256>>>();
    k_fill<<<(NE + 255) / 256, 256>>>(src, dst);

    // proj via mma.sync tf32 + attention
    k_prepW<<<(N_REL * DD * DD + 255) / 256, 256>>>(W_r);
    k_projmma<<<NTILES_M, 256, SM_PROJ>>>(entity_emb);
    k_logits<<<NE / 8, 256>>>(rel_emb, src, dst, et);
    k_att<<<(N_ENT + 7) / 8, 256>>>();

    // layer 0
    k_gather<<<(N_ENT + 7) / 8, 256>>>(entity_emb, DD, 0);
    k_mlp0<<<512, 256, SM_MLP0>>>(entity_emb, W1_0_w, W1_0_b, W2_0_w, W2_0_b, out);

    // layer 1
    k_gather<<<(N_ENT + 7) / 8, 256>>>(out + 64, OUTD, 1);
    k_mlp1<<<512, 256, SM_MLP1>>>(W1_1_w, W1_1_b, W2_1_w, W2_1_b, out);
}

// round 6
// speedup vs baseline: 2.4062x; 1.0088x over previous
#include <cuda_runtime.h>
#include <math.h>
#include <stdint.h>

#define N_ENT 100000
#define N_REL 12
#define DD 64
#define NE 1000000
#define OUTD 160   // 64 + 64 + 32
#define NSCAN ((N_ENT + 1023) / 1024)   // 98
#define TILE_M 128
#define NTILES_M ((N_ENT + TILE_M - 1) / TILE_M)   // 782
#define PITCH 72   // smem row pitch (floats): 72 mod 32 = 8 -> conflict-free LDS.64

// ---------------- device scratch (no allocations allowed) ----------------
__device__ float g_proj[(size_t)N_ENT * N_REL * DD];   // 307.2 MB
__device__ float g_Wt[N_REL * DD * DD];   // W^T, tf32-rounded, fragment-permuted
__device__ float g_logits[NE];            // logits in CSR (dst-sorted) order
__device__ float g_attp[NE];              // att in CSR order
__device__ int4  g_edge[NE];              // CSR slot -> (src, etype, dst, _)
__device__ int   g_cnt[N_ENT];
__device__ int   g_off[N_ENT + 1];
__device__ int   g_cursor[N_ENT];
__device__ int   g_bsum[NSCAN];
__device__ float g_hn0[(size_t)N_ENT * DD];
__device__ float g_hn1[(size_t)N_ENT * DD];

// ---------------- helpers ----------------
__device__ __forceinline__ float leaky(float x) { return x > 0.0f ? x : 0.01f * x; }
__device__ __forceinline__ void fma4(float4& a, float s, float4 w) {
    a.x += s * w.x; a.y += s * w.y; a.z += s * w.z; a.w += s * w.w;
}
__device__ __forceinline__ float to_tf32(float v) {
    float r;
    asm("cvt.rna.tf32.f32 %0, %1;" : "=f"(r) : "f"(v));
    return r;
}
// m16n8k8 row.col tf32 MMA, fp32 accumulate (portable PTX)
__device__ __forceinline__ void mma_tf32(float c[4], uint32_t a0, uint32_t a1,
                                         uint32_t a2, uint32_t a3,
                                         uint32_t b0, uint32_t b1) {
    asm volatile(
        "mma.sync.aligned.m16n8k8.row.col.f32.tf32.tf32.f32 "
        "{%0,%1,%2,%3}, {%4,%5,%6,%7}, {%8,%9}, {%0,%1,%2,%3};"
        : "+f"(c[0]), "+f"(c[1]), "+f"(c[2]), "+f"(c[3])
        : "r"(a0), "r"(a1), "r"(a2), "r"(a3), "r"(b0), "r"(b1));
}

// ---------------- CSR build ----------------
__global__ void k_init() {
    int i = blockIdx.x * blockDim.x + threadIdx.x;
    if (i < N_ENT) g_cnt[i] = 0;
}

__global__ void k_hist(const int* __restrict__ dst) {
    int e = blockIdx.x * 256 + threadIdx.x;
    if (e < NE) atomicAdd(&g_cnt[dst[e]], 1);
}

__global__ void k_scan1() {
    __shared__ int s[1024];
    int i = blockIdx.x * 1024 + threadIdx.x;
    int v = (i < N_ENT) ? g_cnt[i] : 0;
    s[threadIdx.x] = v;
    __syncthreads();
    for (int off = 1; off < 1024; off <<= 1) {
        int t = (threadIdx.x >= off) ? s[threadIdx.x - off] : 0;
        __syncthreads();
        s[threadIdx.x] += t;
        __syncthreads();
    }
    if (i < N_ENT) g_off[i] = s[threadIdx.x] - v;
    if (threadIdx.x == 1023) g_bsum[blockIdx.x] = s[1023];
}

__global__ void k_scan2() {
    __shared__ int s[128];
    int t = threadIdx.x;
    int v0 = (t < NSCAN) ? g_bsum[t] : 0;
    s[t] = v0;
    __syncthreads();
    for (int off = 1; off < 128; off <<= 1) {
        int v = (t >= off) ? s[t - off] : 0;
        __syncthreads();
        s[t] += v;
        __syncthreads();
    }
    if (t < NSCAN) g_bsum[t] = s[t] - v0;   // exclusive
}

__global__ void k_scan3() {
    int i = blockIdx.x * 256 + threadIdx.x;
    if (i < N_ENT) {
        int o = g_off[i] + g_bsum[i >> 10];
        g_off[i] = o;
        g_cursor[i] = o;
    }
    if (i == 0) g_off[N_ENT] = NE;
}

__global__ void k_fill(const int* __restrict__ src, const int* __restrict__ dst,
                       const int* __restrict__ et) {
    int e = blockIdx.x * 256 + threadIdx.x;
    if (e < NE) {
        int d = dst[e];
        int pos = atomicAdd(&g_cursor[d], 1);
        g_edge[pos] = make_int4(src[e], et[e], d, 0);
    }
}

// ---------------- W prep: permuted W^T, tf32-rounded ----------------
// perm(k) = (k>>3)*8 + (k&3)*2 + ((k&7)>>2): thread fragment pair (k, k+4) adjacent
__global__ void k_prepW(const float* __restrict__ Wr) {
    int idx = blockIdx.x * 256 + threadIdx.x;
    if (idx >= N_REL * DD * DD) return;
    int r = idx >> 12;
    int e = idx & 4095;
    int d = e >> 6, j = e & 63;         // source element W[r][d][j]
    int pd = (d >> 3) * 8 + (d & 3) * 2 + ((d & 7) >> 2);
    g_Wt[r * 4096 + j * DD + pd] = to_tf32(Wr[idx]);
}

// ---------------- tf32 mma.sync proj: one 128-node tile per CTA, all 12 r --
// 256 threads = 8 warps; warp w computes rows [w*16, w*16+16) x 64 cols.
// smem rows fragment-permuted, pitch 72 -> all fragment LDS.64 conflict-free.
__global__ void k_projmma(const float* __restrict__ emb) {
    extern __shared__ float smA[];           // [128][PITCH]
    float* smW = smA + 128 * PITCH;          // [64][PITCH]
    const int tid = threadIdx.x;
    const int wid = tid >> 5, lane = tid & 31;
    const int g = lane >> 2, t4 = lane & 3;
    const int n0 = blockIdx.x * TILE_M;

    // stage A tile (zero-fill OOB rows), tf32-rounded, fragment-permuted
    for (int idx = tid; idx < TILE_M * 16; idx += 256) {
        int m = idx >> 4, c = idx & 15;
        float4 v = make_float4(0.f, 0.f, 0.f, 0.f);
        if (n0 + m < N_ENT) v = ((const float4*)(emb + (size_t)(n0 + m) * DD))[c];
        int k0 = c * 4;
        int base = m * PITCH + (k0 >> 3) * 8 + ((k0 & 7) >> 2);
        smA[base]     = to_tf32(v.x);
        smA[base + 2] = to_tf32(v.y);
        smA[base + 4] = to_tf32(v.z);
        smA[base + 6] = to_tf32(v.w);
    }
    __syncthreads();

    const int mb = wid * 16;
    const int row0 = n0 + mb + g;
    const int row1 = row0 + 8;

    for (int r = 0; r < N_REL; r++) {
        // verbatim float4 copy of pre-permuted W^T_r (16KB, L2-resident)
        for (int q = tid; q < 64 * 16; q += 256) {
            int row = q >> 4, c = q & 15;
            *(float4*)&smW[row * PITCH + c * 4] =
                ((const float4*)(g_Wt + r * 4096 + row * 64))[c];
        }
        __syncthreads();

        float acc[8][4];
#pragma unroll
        for (int nt = 0; nt < 8; nt++)
#pragma unroll
            for (int q = 0; q < 4; q++) acc[nt][q] = 0.f;

#pragma unroll
        for (int ks = 0; ks < 8; ks++) {
            float2 pa0 = *(const float2*)&smA[(mb + g)     * PITCH + ks * 8 + t4 * 2];
            float2 pa1 = *(const float2*)&smA[(mb + g + 8) * PITCH + ks * 8 + t4 * 2];
            uint32_t a0 = __float_as_uint(pa0.x), a2 = __float_as_uint(pa0.y);
            uint32_t a1 = __float_as_uint(pa1.x), a3 = __float_as_uint(pa1.y);
#pragma unroll
            for (int nt = 0; nt < 8; nt++) {
                float2 pb = *(const float2*)&smW[(nt * 8 + g) * PITCH + ks * 8 + t4 * 2];
                mma_tf32(acc[nt], a0, a1, a2, a3,
                         __float_as_uint(pb.x), __float_as_uint(pb.y));
            }
        }

        if (row0 < N_ENT) {
            float* base = g_proj + ((size_t)row0 * N_REL + r) * DD;
#pragma unroll
            for (int nt = 0; nt < 8; nt++)
                *(float2*)&base[nt * 8 + t4 * 2] = make_float2(acc[nt][0], acc[nt][1]);
        }
        if (row1 < N_ENT) {
            float* base = g_proj + ((size_t)row1 * N_REL + r) * DD;
#pragma unroll
            for (int nt = 0; nt < 8; nt++)
                *(float2*)&base[nt * 8 + t4 * 2] = make_float2(acc[nt][2], acc[nt][3]);
        }
        __syncthreads();
    }
}

// ---------------- per-edge logits in CSR order (head rows L1-reuse) -------
__global__ void k_logits(const float* __restrict__ rel_emb) {
    int p = blockIdx.x * 8 + (threadIdx.x >> 5);
    if (p >= NE) return;
    int l = threadIdx.x & 31;
    int4 e = g_edge[p];                      // broadcast 16B load
    int s = e.x, r = e.y, d = e.z;
    const float* pt = g_proj + ((size_t)s * N_REL + r) * DD;
    const float* ph = g_proj + ((size_t)d * N_REL + r) * DD;
    const float* pr = rel_emb + (size_t)r * DD;

    float sum = pt[l]      * tanhf(ph[l]      + pr[l])
              + pt[l + 32] * tanhf(ph[l + 32] + pr[l + 32]);
#pragma unroll
    for (int o = 16; o; o >>= 1) sum += __shfl_xor_sync(0xffffffffu, sum, o);
    if (l == 0) g_logits[p] = sum;
}

// ---------------- fused softmax + layer-0 gather (warp per node) ----------
// computes att (stored for layer 1) and h_n0 = sum att * emb[src]
__global__ void k_attgather(const float* __restrict__ emb) {
    int n = blockIdx.x * 8 + (threadIdx.x >> 5);
    if (n >= N_ENT) return;
    int l = threadIdx.x & 31;
    int beg = g_off[n], end = g_off[n + 1];
    float a0 = 0.f, a1 = 0.f;

    if (beg < end) {
        float mx = -INFINITY;
        for (int p = beg + l; p < end; p += 32) mx = fmaxf(mx, g_logits[p]);
#pragma unroll
        for (int o = 16; o; o >>= 1) mx = fmaxf(mx, __shfl_xor_sync(0xffffffffu, mx, o));

        float s = 0.f;
        for (int p = beg + l; p < end; p += 32) s += expf(g_logits[p] - mx);
#pragma unroll
        for (int o = 16; o; o >>= 1) s += __shfl_xor_sync(0xffffffffu, s, o);
        float inv = 1.0f / s;

        for (int p = beg + l; p < end; p += 32)
            g_attp[p] = expf(g_logits[p] - mx) * inv;

        for (int p = beg; p < end; p++) {
            float att = expf(g_logits[p] - mx) * inv;   // broadcast L1 hit
            const float* xs = emb + (size_t)g_edge[p].x * DD;
            a0 += att * xs[l];
            a1 += att * xs[l + 32];
        }
    }
    g_hn0[(size_t)n * DD + l]      = a0;
    g_hn0[(size_t)n * DD + l + 32] = a1;
}

// ---------------- layer-1 gather: h_n1 = sum att * x1[src] ----------------
__global__ void k_gather1(const float* __restrict__ xbase) {
    int n = blockIdx.x * 8 + (threadIdx.x >> 5);
    if (n >= N_ENT) return;
    int l = threadIdx.x & 31;
    int beg = g_off[n], end = g_off[n + 1];
    float a0 = 0.f, a1 = 0.f;
    for (int p = beg; p < end; p++) {
        float att = g_attp[p];
        const float* xs = xbase + (size_t)g_edge[p].x * OUTD;
        a0 += att * xs[l];
        a1 += att * xs[l + 32];
    }
    g_hn1[(size_t)n * DD + l]      = a0;
    g_hn1[(size_t)n * DD + l + 32] = a1;
}

// ---------------- layer 0 MLP ----------------
__global__ void k_mlp0(const float* __restrict__ x0,
                       const float* __restrict__ W1, const float* __restrict__ b1,
                       const float* __restrict__ W2, const float* __restrict__ b2,
                       float* __restrict__ out) {
    extern __shared__ float dsm[];
    float* W1s = dsm;
    float* W2s = dsm + 64 * 68;
    float* sa  = dsm + 2 * 64 * 68;
    float* sm_ = dsm + 3 * 64 * 68;
    const int tid = threadIdx.x;

    for (int idx = tid; idx < DD * DD; idx += 256) {
        int j = idx >> 6, d = idx & 63;
        W1s[d * 68 + j] = W1[idx];
        W2s[d * 68 + j] = W2[idx];
    }
    __syncthreads();

    const int jg = tid & 15, vg = tid >> 4;
    const int j0 = jg * 4;
    const float4 b1v = *(const float4*)&b1[j0];
    const float4 b2v = *(const float4*)&b2[j0];
    const int NT = (N_ENT + 63) / 64;

    for (int t = blockIdx.x; t < NT; t += gridDim.x) {
        int n0 = t * 64;
        for (int q = tid; q < 64 * 16; q += 256) {
            int v = q >> 4, c = q & 15;
            int n = n0 + v;
            float4 xv = make_float4(0.f, 0.f, 0.f, 0.f), hv = xv;
            if (n < N_ENT) {
                xv = ((const float4*)(x0 + (size_t)n * DD))[c];
                hv = ((const float4*)(g_hn0 + (size_t)n * DD))[c];
                ((float4*)(out + (size_t)n * OUTD))[c] = xv;
            }
            *(float4*)&sa [v * 68 + c * 4] = make_float4(xv.x + hv.x, xv.y + hv.y, xv.z + hv.z, xv.w + hv.w);
            *(float4*)&sm_[v * 68 + c * 4] = make_float4(xv.x * hv.x, xv.y * hv.y, xv.z * hv.z, xv.w * hv.w);
        }
        __syncthreads();

        float4 acc_a[4] = {}, acc_m[4] = {};
#pragma unroll
        for (int d4 = 0; d4 < 16; d4++) {
            float4 ea[4], em[4];
#pragma unroll
            for (int vv = 0; vv < 4; vv++) {
                ea[vv] = *(const float4*)&sa [(vg * 4 + vv) * 68 + d4 * 4];
                em[vv] = *(const float4*)&sm_[(vg * 4 + vv) * 68 + d4 * 4];
            }
#pragma unroll
            for (int dd = 0; dd < 4; dd++) {
                float4 w1 = *(const float4*)&W1s[(d4 * 4 + dd) * 68 + j0];
                float4 w2 = *(const float4*)&W2s[(d4 * 4 + dd) * 68 + j0];
#pragma unroll
                for (int vv = 0; vv < 4; vv++) {
                    float sA = dd == 0 ? ea[vv].x : dd == 1 ? ea[vv].y : dd == 2 ? ea[vv].z : ea[vv].w;
                    float sM = dd == 0 ? em[vv].x : dd == 1 ? em[vv].y : dd == 2 ? em[vv].z : em[vv].w;
                    fma4(acc_a[vv], sA, w1);
                    fma4(acc_m[vv], sM, w2);
                }
            }
        }
#pragma unroll
        for (int vv = 0; vv < 4; vv++) {
            int n = n0 + vg * 4 + vv;
            if (n < N_ENT) {
                float4 r;
                r.x = leaky(acc_a[vv].x + b1v.x) + leaky(acc_m[vv].x + b2v.x);
                r.y = leaky(acc_a[vv].y + b1v.y) + leaky(acc_m[vv].y + b2v.y);
                r.z = leaky(acc_a[vv].z + b1v.z) + leaky(acc_m[vv].z + b2v.z);
                r.w = leaky(acc_a[vv].w + b1v.w) + leaky(acc_m[vv].w + b2v.w);
                *(float4*)&out[(size_t)n * OUTD + 64 + j0] = r;
            }
        }
        __syncthreads();
    }
}

// ---------------- layer 1 MLP (out dim 32) ----------------
__global__ void k_mlp1(const float* __restrict__ W1, const float* __restrict__ b1,
                       const float* __restrict__ W2, const float* __restrict__ b2,
                       float* __restrict__ out) {
    extern __shared__ float dsm[];
    float* W1s = dsm;
    float* W2s = dsm + 64 * 36;
    float* sa  = dsm + 2 * 64 * 36;
    float* sm_ = dsm + 2 * 64 * 36 + 64 * 68;
    const int tid = threadIdx.x;

    for (int idx = tid; idx < 32 * DD; idx += 256) {
        int j = idx >> 6, d = idx & 63;
        W1s[d * 36 + j] = W1[idx];
        W2s[d * 36 + j] = W2[idx];
    }
    __syncthreads();

    const int jg = tid & 7, vgp = tid >> 3;
    const int j0 = jg * 4;
    const float4 b1v = *(const float4*)&b1[j0];
    const float4 b2v = *(const float4*)&b2[j0];
    const int NT = (N_ENT + 63) / 64;

    for (int t = blockIdx.x; t < NT; t += gridDim.x) {
        int n0 = t * 64;
        for (int q = tid; q < 64 * 16; q += 256) {
            int v = q >> 4, c = q & 15;
            int n = n0 + v;
            float4 xv = make_float4(0.f, 0.f, 0.f, 0.f), hv = xv;
            if (n < N_ENT) {
                xv = ((const float4*)(out + (size_t)n * OUTD + 64))[c];
                hv = ((const float4*)(g_hn1 + (size_t)n * DD))[c];
            }
            *(float4*)&sa [v * 68 + c * 4] = make_float4(xv.x + hv.x, xv.y + hv.y, xv.z + hv.z, xv.w + hv.w);
            *(float4*)&sm_[v * 68 + c * 4] = make_float4(xv.x * hv.x, xv.y * hv.y, xv.z * hv.z, xv.w * hv.w);
        }
        __syncthreads();

        float4 acc_a[2] = {}, acc_m[2] = {};
#pragma unroll
        for (int d4 = 0; d4 < 16; d4++) {
            float4 ea[2], em[2];
#pragma unroll
            for (int vv = 0; vv < 2; vv++) {
                ea[vv] = *(const float4*)&sa [(vgp * 2 + vv) * 68 + d4 * 4];
                em[vv] = *(const float4*)&sm_[(vgp * 2 + vv) * 68 + d4 * 4];
            }
#pragma unroll
            for (int dd = 0; dd < 4; dd++) {
                float4 w1 = *(const float4*)&W1s[(d4 * 4 + dd) * 36 + j0];
                float4 w2 = *(const float4*)&W2s[(d4 * 4 + dd) * 36 + j0];
#pragma unroll
                for (int vv = 0; vv < 2; vv++) {
                    float sA = dd == 0 ? ea[vv].x : dd == 1 ? ea[vv].y : dd == 2 ? ea[vv].z : ea[vv].w;
                    float sM = dd == 0 ? em[vv].x : dd == 1 ? em[vv].y : dd == 2 ? em[vv].z : em[vv].w;
                    fma4(acc_a[vv], sA, w1);
                    fma4(acc_m[vv], sM, w2);
                }
            }
        }
#pragma unroll
        for (int vv = 0; vv < 2; vv++) {
            int n = n0 + vgp * 2 + vv;
            if (n < N_ENT) {
                float4 r;
                r.x = leaky(acc_a[vv].x + b1v.x) + leaky(acc_m[vv].x + b2v.x);
                r.y = leaky(acc_a[vv].y + b1v.y) + leaky(acc_m[vv].y + b2v.y);
                r.z = leaky(acc_a[vv].z + b1v.z) + leaky(acc_m[vv].z + b2v.z);
                r.w = leaky(acc_a[vv].w + b1v.w) + leaky(acc_m[vv].w + b2v.w);
                *(float4*)&out[(size_t)n * OUTD + 128 + j0] = r;
            }
        }
        __syncthreads();
    }
}

// ---------------- launch ----------------
extern "C" void kernel_launch(void* const* d_in, const int* in_sizes, int n_in,
                              void* d_out, int out_size) {
    const float* entity_emb = (const float*)d_in[0];
    const float* rel_emb    = (const float*)d_in[1];
    const float* W_r        = (const float*)d_in[2];
    const float* W1_0_w     = (const float*)d_in[3];
    const float* W1_0_b     = (const float*)d_in[4];
    const float* W2_0_w     = (const float*)d_in[5];
    const float* W2_0_b     = (const float*)d_in[6];
    const float* W1_1_w     = (const float*)d_in[7];
    const float* W1_1_b     = (const float*)d_in[8];
    const float* W2_1_w     = (const float*)d_in[9];
    const float* W2_1_b     = (const float*)d_in[10];
    const int*   src        = (const int*)d_in[11];
    const int*   dst        = (const int*)d_in[12];
    const int*   et         = (const int*)d_in[13];
    float* out = (float*)d_out;

    const int SM_PROJ = (128 * PITCH + 64 * PITCH) * 4;  // 55296 B
    const int SM_MLP0 = 4 * 64 * 68 * 4;                 // 69632 B
    const int SM_MLP1 = (2 * 64 * 36 + 2 * 64 * 68) * 4; // 53248 B
    cudaFuncSetAttribute(k_projmma, cudaFuncAttributeMaxDynamicSharedMemorySize, SM_PROJ);
    cudaFuncSetAttribute(k_mlp0, cudaFuncAttributeMaxDynamicSharedMemorySize, SM_MLP0);
    cudaFuncSetAttribute(k_mlp1, cudaFuncAttributeMaxDynamicSharedMemorySize, SM_MLP1);

    // CSR build (counting sort by dst)
    k_init<<<(N_ENT + 255) / 256, 256>>>();
    k_hist<<<(NE + 255) / 256, 256>>>(dst);
    k_scan1<<<NSCAN, 1024>>>();
    k_scan2<<<1, 128>>>();
    k_scan3<<<(N_ENT + 255) / 256, 256>>>();
    k_fill<<<(NE + 255) / 256, 256>>>(src, dst, et);

    // proj via mma.sync tf32, then CSR-ordered attention
    k_prepW<<<(N_REL * DD * DD + 255) / 256, 256>>>(W_r);
    k_projmma<<<NTILES_M, 256, SM_PROJ>>>(entity_emb);
    k_logits<<<NE / 8, 256>>>(rel_emb);

    // layer 0 (fused softmax + gather)
    k_attgather<<<(N_ENT + 7) / 8, 256>>>(entity_emb);
    k_mlp0<<<512, 256, SM_MLP0>>>(entity_emb, W1_0_w, W1_0_b, W2_0_w, W2_0_b, out);

    // layer 1
    k_gather1<<<(N_ENT + 7) / 8, 256>>>(out + 64);
    k_mlp1<<<512, 256, SM_MLP1>>>(W1_1_w, W1_1_b, W2_1_w, W2_1_b, out);
}

// round 7
// speedup vs baseline: 2.5707x; 1.0684x over previous
#include <cuda_runtime.h>
#include <cuda_fp16.h>
#include <math.h>
#include <stdint.h>

#define N_ENT 100000
#define N_REL 12
#define DD 64
#define NE 1000000
#define OUTD 160   // 64 + 64 + 32
#define NSCAN ((N_ENT + 1023) / 1024)   // 98
#define TILE_M 128
#define NTILES_M ((N_ENT + TILE_M - 1) / TILE_M)   // 782
#define PITCH 72   // smem row pitch (floats): conflict-free fragment LDS.64

// ---------------- device scratch (no allocations allowed) ----------------
__device__ __half g_proj[(size_t)N_ENT * N_REL * DD];  // 153.6 MB (fp16)
__device__ float g_Wt[N_REL * DD * DD];   // W_r^T, tf32-rounded, fragment-permuted
__device__ float g_Wm[2 * DD * DD];       // W1_0^T, W2_0^T permuted tf32
__device__ float g_logits[NE];            // logits in CSR (dst-sorted) order
__device__ float g_attp[NE];              // att in CSR order
__device__ int4  g_edge[NE];              // CSR slot -> (src, etype, dst, _)
__device__ int   g_cnt[N_ENT];
__device__ int   g_off[N_ENT + 1];
__device__ int   g_cursor[N_ENT];
__device__ int   g_bsum[NSCAN];
__device__ float g_hn0[(size_t)N_ENT * DD];
__device__ float g_hn1[(size_t)N_ENT * DD];

// ---------------- helpers ----------------
__device__ __forceinline__ float leaky(float x) { return x > 0.0f ? x : 0.01f * x; }
__device__ __forceinline__ void fma4(float4& a, float s, float4 w) {
    a.x += s * w.x; a.y += s * w.y; a.z += s * w.z; a.w += s * w.w;
}
__device__ __forceinline__ float to_tf32(float v) {
    float r;
    asm("cvt.rna.tf32.f32 %0, %1;" : "=f"(r) : "f"(v));
    return r;
}
__device__ __forceinline__ float ftanh(float x) {
    x = fminf(fmaxf(x, -20.f), 20.f);
    float e = __expf(2.f * x);
    return (e - 1.f) / (e + 1.f);
}
// m16n8k8 row.col tf32 MMA, fp32 accumulate (portable PTX)
__device__ __forceinline__ void mma_tf32(float c[4], uint32_t a0, uint32_t a1,
                                         uint32_t a2, uint32_t a3,
                                         uint32_t b0, uint32_t b1) {
    asm volatile(
        "mma.sync.aligned.m16n8k8.row.col.f32.tf32.tf32.f32 "
        "{%0,%1,%2,%3}, {%4,%5,%6,%7}, {%8,%9}, {%0,%1,%2,%3};"
        : "+f"(c[0]), "+f"(c[1]), "+f"(c[2]), "+f"(c[3])
        : "r"(a0), "r"(a1), "r"(a2), "r"(a3), "r"(b0), "r"(b1));
}

// ---------------- CSR build ----------------
__global__ void k_init() {
    int i = blockIdx.x * blockDim.x + threadIdx.x;
    if (i < N_ENT) g_cnt[i] = 0;
}

__global__ void k_hist(const int* __restrict__ dst) {
    int e = blockIdx.x * 256 + threadIdx.x;
    if (e < NE) atomicAdd(&g_cnt[dst[e]], 1);
}

__global__ void k_scan1() {
    __shared__ int s[1024];
    int i = blockIdx.x * 1024 + threadIdx.x;
    int v = (i < N_ENT) ? g_cnt[i] : 0;
    s[threadIdx.x] = v;
    __syncthreads();
    for (int off = 1; off < 1024; off <<= 1) {
        int t = (threadIdx.x >= off) ? s[threadIdx.x - off] : 0;
        __syncthreads();
        s[threadIdx.x] += t;
        __syncthreads();
    }
    if (i < N_ENT) g_off[i] = s[threadIdx.x] - v;
    if (threadIdx.x == 1023) g_bsum[blockIdx.x] = s[1023];
}

__global__ void k_scan2() {
    __shared__ int s[128];
    int t = threadIdx.x;
    int v0 = (t < NSCAN) ? g_bsum[t] : 0;
    s[t] = v0;
    __syncthreads();
    for (int off = 1; off < 128; off <<= 1) {
        int v = (t >= off) ? s[t - off] : 0;
        __syncthreads();
        s[t] += v;
        __syncthreads();
    }
    if (t < NSCAN) g_bsum[t] = s[t] - v0;   // exclusive
}

__global__ void k_scan3() {
    int i = blockIdx.x * 256 + threadIdx.x;
    if (i < N_ENT) {
        int o = g_off[i] + g_bsum[i >> 10];
        g_off[i] = o;
        g_cursor[i] = o;
    }
    if (i == 0) g_off[N_ENT] = NE;
}

__global__ void k_fill(const int* __restrict__ src, const int* __restrict__ dst,
                       const int* __restrict__ et) {
    int e = blockIdx.x * 256 + threadIdx.x;
    if (e < NE) {
        int d = dst[e];
        int pos = atomicAdd(&g_cursor[d], 1);
        g_edge[pos] = make_int4(src[e], et[e], d, 0);
    }
}

// ---------------- W preps: permuted W^T, tf32-rounded ----------------
// perm(k) = (k>>3)*8 + (k&3)*2 + ((k&7)>>2)
__global__ void k_prepW(const float* __restrict__ Wr) {
    int idx = blockIdx.x * 256 + threadIdx.x;
    if (idx >= N_REL * DD * DD) return;
    int r = idx >> 12;
    int e = idx & 4095;
    int d = e >> 6, j = e & 63;         // source element W[r][d][j]
    int pd = (d >> 3) * 8 + (d & 3) * 2 + ((d & 7) >> 2);
    g_Wt[r * 4096 + j * DD + pd] = to_tf32(Wr[idx]);
}

__global__ void k_prepWm(const float* __restrict__ W1, const float* __restrict__ W2) {
    int idx = blockIdx.x * 256 + threadIdx.x;
    if (idx >= 2 * DD * DD) return;
    const float* srcw = (idx < 4096) ? W1 : W2;
    int e = idx & 4095;
    int j = e >> 6, d = e & 63;         // W[j][d] row-major
    int pd = (d >> 3) * 8 + (d & 3) * 2 + ((d & 7) >> 2);
    g_Wm[(idx >> 12) * 4096 + j * DD + pd] = to_tf32(srcw[e]);
}

// ---------------- tf32 mma.sync proj (A fragments in registers) ----------
__global__ void k_projmma(const float* __restrict__ emb) {
    extern __shared__ float smA[];           // [128][PITCH]
    float* smW = smA + 128 * PITCH;          // [64][PITCH]
    const int tid = threadIdx.x;
    const int wid = tid >> 5, lane = tid & 31;
    const int g = lane >> 2, t4 = lane & 3;
    const int n0 = blockIdx.x * TILE_M;

    // stage A tile (zero-fill OOB), tf32-rounded, fragment-permuted
    for (int idx = tid; idx < TILE_M * 16; idx += 256) {
        int m = idx >> 4, c = idx & 15;
        float4 v = make_float4(0.f, 0.f, 0.f, 0.f);
        if (n0 + m < N_ENT) v = ((const float4*)(emb + (size_t)(n0 + m) * DD))[c];
        int k0 = c * 4;
        int base = m * PITCH + (k0 >> 3) * 8 + ((k0 & 7) >> 2);
        smA[base]     = to_tf32(v.x);
        smA[base + 2] = to_tf32(v.y);
        smA[base + 4] = to_tf32(v.z);
        smA[base + 6] = to_tf32(v.w);
    }
    __syncthreads();

    const int mb = wid * 16;
    const int row0 = n0 + mb + g;
    const int row1 = row0 + 8;

    // hoist A fragments into registers (reused across all 12 relations)
    uint32_t af[8][4];
#pragma unroll
    for (int ks = 0; ks < 8; ks++) {
        float2 pa0 = *(const float2*)&smA[(mb + g)     * PITCH + ks * 8 + t4 * 2];
        float2 pa1 = *(const float2*)&smA[(mb + g + 8) * PITCH + ks * 8 + t4 * 2];
        af[ks][0] = __float_as_uint(pa0.x);
        af[ks][1] = __float_as_uint(pa1.x);
        af[ks][2] = __float_as_uint(pa0.y);
        af[ks][3] = __float_as_uint(pa1.y);
    }

    for (int r = 0; r < N_REL; r++) {
        for (int q = tid; q < 64 * 16; q += 256) {
            int row = q >> 4, c = q & 15;
            *(float4*)&smW[row * PITCH + c * 4] =
                ((const float4*)(g_Wt + r * 4096 + row * 64))[c];
        }
        __syncthreads();

        float acc[8][4];
#pragma unroll
        for (int nt = 0; nt < 8; nt++)
#pragma unroll
            for (int q = 0; q < 4; q++) acc[nt][q] = 0.f;

#pragma unroll
        for (int ks = 0; ks < 8; ks++) {
#pragma unroll
            for (int nt = 0; nt < 8; nt++) {
                float2 pb = *(const float2*)&smW[(nt * 8 + g) * PITCH + ks * 8 + t4 * 2];
                mma_tf32(acc[nt], af[ks][0], af[ks][1], af[ks][2], af[ks][3],
                         __float_as_uint(pb.x), __float_as_uint(pb.y));
            }
        }

        if (row0 < N_ENT) {
            __half2* base = (__half2*)(g_proj + ((size_t)row0 * N_REL + r) * DD);
#pragma unroll
            for (int nt = 0; nt < 8; nt++)
                base[nt * 4 + t4] = __floats2half2_rn(acc[nt][0], acc[nt][1]);
        }
        if (row1 < N_ENT) {
            __half2* base = (__half2*)(g_proj + ((size_t)row1 * N_REL + r) * DD);
#pragma unroll
            for (int nt = 0; nt < 8; nt++)
                base[nt * 4 + t4] = __floats2half2_rn(acc[nt][2], acc[nt][3]);
        }
        __syncthreads();
    }
}

// ---------------- per-edge logits in CSR order (fp16 proj, fast tanh) -----
__global__ void k_logits(const float* __restrict__ rel_emb) {
    int p = blockIdx.x * 8 + (threadIdx.x >> 5);
    if (p >= NE) return;
    int l = threadIdx.x & 31;
    int4 e = g_edge[p];
    int s = e.x, r = e.y, d = e.z;
    const __half2* pt = (const __half2*)(g_proj + ((size_t)s * N_REL + r) * DD);
    const __half2* ph = (const __half2*)(g_proj + ((size_t)d * N_REL + r) * DD);
    float2 pr = ((const float2*)(rel_emb + (size_t)r * DD))[l];
    float2 tv = __half22float2(pt[l]);
    float2 hv = __half22float2(ph[l]);

    float sum = tv.x * ftanh(hv.x + pr.x) + tv.y * ftanh(hv.y + pr.y);
#pragma unroll
    for (int o = 16; o; o >>= 1) sum += __shfl_xor_sync(0xffffffffu, sum, o);
    if (l == 0) g_logits[p] = sum;
}

// ---------------- fused softmax + layer-0 gather (warp per node) ----------
__global__ void k_attgather(const float* __restrict__ emb) {
    int n = blockIdx.x * 8 + (threadIdx.x >> 5);
    if (n >= N_ENT) return;
    int l = threadIdx.x & 31;
    int beg = g_off[n], end = g_off[n + 1];
    float a0 = 0.f, a1 = 0.f;

    if (beg < end) {
        float mx = -INFINITY;
        for (int p = beg + l; p < end; p += 32) mx = fmaxf(mx, g_logits[p]);
#pragma unroll
        for (int o = 16; o; o >>= 1) mx = fmaxf(mx, __shfl_xor_sync(0xffffffffu, mx, o));

        float s = 0.f;
        for (int p = beg + l; p < end; p += 32) s += __expf(g_logits[p] - mx);
#pragma unroll
        for (int o = 16; o; o >>= 1) s += __shfl_xor_sync(0xffffffffu, s, o);
        float inv = 1.0f / s;

        for (int p = beg + l; p < end; p += 32)
            g_attp[p] = __expf(g_logits[p] - mx) * inv;

        for (int p = beg; p < end; p++) {
            float att = __expf(g_logits[p] - mx) * inv;
            const float* xs = emb + (size_t)g_edge[p].x * DD;
            a0 += att * xs[l];
            a1 += att * xs[l + 32];
        }
    }
    g_hn0[(size_t)n * DD + l]      = a0;
    g_hn0[(size_t)n * DD + l + 32] = a1;
}

// ---------------- layer-1 gather ----------------
__global__ void k_gather1(const float* __restrict__ xbase) {
    int n = blockIdx.x * 8 + (threadIdx.x >> 5);
    if (n >= N_ENT) return;
    int l = threadIdx.x & 31;
    int beg = g_off[n], end = g_off[n + 1];
    float a0 = 0.f, a1 = 0.f;
    for (int p = beg; p < end; p++) {
        float att = g_attp[p];
        const float* xs = xbase + (size_t)g_edge[p].x * OUTD;
        a0 += att * xs[l];
        a1 += att * xs[l + 32];
    }
    g_hn1[(size_t)n * DD + l]      = a0;
    g_hn1[(size_t)n * DD + l + 32] = a1;
}

// ---------------- layer 0 MLP via tf32 mma.sync ----------------
// smem: smAdd[128][PITCH], smMul[128][PITCH], smW1[64][PITCH], smW2[64][PITCH]
__global__ void k_mlp0mma(const float* __restrict__ x0,
                          const float* __restrict__ b1, const float* __restrict__ b2,
                          float* __restrict__ out) {
    extern __shared__ float dsm[];
    float* smAdd = dsm;
    float* smMul = dsm + 128 * PITCH;
    float* smW1  = dsm + 2 * 128 * PITCH;
    float* smW2  = smW1 + 64 * PITCH;
    const int tid = threadIdx.x;
    const int wid = tid >> 5, lane = tid & 31;
    const int g = lane >> 2, t4 = lane & 3;
    const int n0 = blockIdx.x * TILE_M;

    // stage add/mul tiles (tf32-permuted) + copy x0 to out[:,0:64]
    for (int idx = tid; idx < TILE_M * 16; idx += 256) {
        int m = idx >> 4, c = idx & 15;
        int n = n0 + m;
        float4 xv = make_float4(0.f, 0.f, 0.f, 0.f), hv = xv;
        if (n < N_ENT) {
            xv = ((const float4*)(x0 + (size_t)n * DD))[c];
            hv = ((const float4*)(g_hn0 + (size_t)n * DD))[c];
            ((float4*)(out + (size_t)n * OUTD))[c] = xv;
        }
        int k0 = c * 4;
        int base = m * PITCH + (k0 >> 3) * 8 + ((k0 & 7) >> 2);
        smAdd[base]     = to_tf32(xv.x + hv.x);
        smAdd[base + 2] = to_tf32(xv.y + hv.y);
        smAdd[base + 4] = to_tf32(xv.z + hv.z);
        smAdd[base + 6] = to_tf32(xv.w + hv.w);
        smMul[base]     = to_tf32(xv.x * hv.x);
        smMul[base + 2] = to_tf32(xv.y * hv.y);
        smMul[base + 4] = to_tf32(xv.z * hv.z);
        smMul[base + 6] = to_tf32(xv.w * hv.w);
    }
    // stage W1, W2 (pre-permuted tf32)
    for (int q = tid; q < 64 * 16; q += 256) {
        int row = q >> 4, c = q & 15;
        *(float4*)&smW1[row * PITCH + c * 4] = ((const float4*)(g_Wm + row * 64))[c];
        *(float4*)&smW2[row * PITCH + c * 4] = ((const float4*)(g_Wm + 4096 + row * 64))[c];
    }
    __syncthreads();

    const int mb = wid * 16;
    const int row0 = n0 + mb + g;
    const int row1 = row0 + 8;

    float acc_a[8][4], acc_m[8][4];
#pragma unroll
    for (int nt = 0; nt < 8; nt++)
#pragma unroll
        for (int q = 0; q < 4; q++) { acc_a[nt][q] = 0.f; acc_m[nt][q] = 0.f; }

#pragma unroll
    for (int ks = 0; ks < 8; ks++) {
        float2 pa0 = *(const float2*)&smAdd[(mb + g)     * PITCH + ks * 8 + t4 * 2];
        float2 pa1 = *(const float2*)&smAdd[(mb + g + 8) * PITCH + ks * 8 + t4 * 2];
        float2 pm0 = *(const float2*)&smMul[(mb + g)     * PITCH + ks * 8 + t4 * 2];
        float2 pm1 = *(const float2*)&smMul[(mb + g + 8) * PITCH + ks * 8 + t4 * 2];
        uint32_t aa0 = __float_as_uint(pa0.x), aa1 = __float_as_uint(pa1.x);
        uint32_t aa2 = __float_as_uint(pa0.y), aa3 = __float_as_uint(pa1.y);
        uint32_t am0 = __float_as_uint(pm0.x), am1 = __float_as_uint(pm1.x);
        uint32_t am2 = __float_as_uint(pm0.y), am3 = __float_as_uint(pm1.y);
#pragma unroll
        for (int nt = 0; nt < 8; nt++) {
            float2 pb1 = *(const float2*)&smW1[(nt * 8 + g) * PITCH + ks * 8 + t4 * 2];
            float2 pb2 = *(const float2*)&smW2[(nt * 8 + g) * PITCH + ks * 8 + t4 * 2];
            mma_tf32(acc_a[nt], aa0, aa1, aa2, aa3,
                     __float_as_uint(pb1.x), __float_as_uint(pb1.y));
            mma_tf32(acc_m[nt], am0, am1, am2, am3,
                     __float_as_uint(pb2.x), __float_as_uint(pb2.y));
        }
    }

    // epilogue: y = leaky(add + b1) + leaky(mul + b2) -> out[:, 64:128]
#pragma unroll
    for (int nt = 0; nt < 8; nt++) {
        int j = nt * 8 + t4 * 2;
        float2 bb1 = *(const float2*)&b1[j];
        float2 bb2 = *(const float2*)&b2[j];
        if (row0 < N_ENT) {
            float2 y;
            y.x = leaky(acc_a[nt][0] + bb1.x) + leaky(acc_m[nt][0] + bb2.x);
            y.y = leaky(acc_a[nt][1] + bb1.y) + leaky(acc_m[nt][1] + bb2.y);
            *(float2*)&out[(size_t)row0 * OUTD + 64 + j] = y;
        }
        if (row1 < N_ENT) {
            float2 y;
            y.x = leaky(acc_a[nt][2] + bb1.x) + leaky(acc_m[nt][2] + bb2.x);
            y.y = leaky(acc_a[nt][3] + bb1.y) + leaky(acc_m[nt][3] + bb2.y);
            *(float2*)&out[(size_t)row1 * OUTD + 64 + j] = y;
        }
    }
}

// ---------------- layer 1 MLP (out dim 32, FFMA) ----------------
__global__ void k_mlp1(const float* __restrict__ W1, const float* __restrict__ b1,
                       const float* __restrict__ W2, const float* __restrict__ b2,
                       float* __restrict__ out) {
    extern __shared__ float dsm[];
    float* W1s = dsm;
    float* W2s = dsm + 64 * 36;
    float* sa  = dsm + 2 * 64 * 36;
    float* sm_ = dsm + 2 * 64 * 36 + 64 * 68;
    const int tid = threadIdx.x;

    for (int idx = tid; idx < 32 * DD; idx += 256) {
        int j = idx >> 6, d = idx & 63;
        W1s[d * 36 + j] = W1[idx];
        W2s[d * 36 + j] = W2[idx];
    }
    __syncthreads();

    const int jg = tid & 7, vgp = tid >> 3;
    const int j0 = jg * 4;
    const float4 b1v = *(const float4*)&b1[j0];
    const float4 b2v = *(const float4*)&b2[j0];
    const int NT = (N_ENT + 63) / 64;

    for (int t = blockIdx.x; t < NT; t += gridDim.x) {
        int n0 = t * 64;
        for (int q = tid; q < 64 * 16; q += 256) {
            int v = q >> 4, c = q & 15;
            int n = n0 + v;
            float4 xv = make_float4(0.f, 0.f, 0.f, 0.f), hv = xv;
            if (n < N_ENT) {
                xv = ((const float4*)(out + (size_t)n * OUTD + 64))[c];
                hv = ((const float4*)(g_hn1 + (size_t)n * DD))[c];
            }
            *(float4*)&sa [v * 68 + c * 4] = make_float4(xv.x + hv.x, xv.y + hv.y, xv.z + hv.z, xv.w + hv.w);
            *(float4*)&sm_[v * 68 + c * 4] = make_float4(xv.x * hv.x, xv.y * hv.y, xv.z * hv.z, xv.w * hv.w);
        }
        __syncthreads();

        float4 acc_a[2] = {}, acc_m[2] = {};
#pragma unroll
        for (int d4 = 0; d4 < 16; d4++) {
            float4 ea[2], em[2];
#pragma unroll
            for (int vv = 0; vv < 2; vv++) {
                ea[vv] = *(const float4*)&sa [(vgp * 2 + vv) * 68 + d4 * 4];
                em[vv] = *(const float4*)&sm_[(vgp * 2 + vv) * 68 + d4 * 4];
            }
#pragma unroll
            for (int dd = 0; dd < 4; dd++) {
                float4 w1 = *(const float4*)&W1s[(d4 * 4 + dd) * 36 + j0];
                float4 w2 = *(const float4*)&W2s[(d4 * 4 + dd) * 36 + j0];
#pragma unroll
                for (int vv = 0; vv < 2; vv++) {
                    float sA = dd == 0 ? ea[vv].x : dd == 1 ? ea[vv].y : dd == 2 ? ea[vv].z : ea[vv].w;
                    float sM = dd == 0 ? em[vv].x : dd == 1 ? em[vv].y : dd == 2 ? em[vv].z : em[vv].w;
                    fma4(acc_a[vv], sA, w1);
                    fma4(acc_m[vv], sM, w2);
                }
            }
        }
#pragma unroll
        for (int vv = 0; vv < 2; vv++) {
            int n = n0 + vgp * 2 + vv;
            if (n < N_ENT) {
                float4 r;
                r.x = leaky(acc_a[vv].x + b1v.x) + leaky(acc_m[vv].x + b2v.x);
                r.y = leaky(acc_a[vv].y + b1v.y) + leaky(acc_m[vv].y + b2v.y);
                r.z = leaky(acc_a[vv].z + b1v.z) + leaky(acc_m[vv].z + b2v.z);
                r.w = leaky(acc_a[vv].w + b1v.w) + leaky(acc_m[vv].w + b2v.w);
                *(float4*)&out[(size_t)n * OUTD + 128 + j0] = r;
            }
        }
        __syncthreads();
    }
}

// ---------------- launch ----------------
extern "C" void kernel_launch(void* const* d_in, const int* in_sizes, int n_in,
                              void* d_out, int out_size) {
    const float* entity_emb = (const float*)d_in[0];
    const float* rel_emb    = (const float*)d_in[1];
    const float* W_r        = (const float*)d_in[2];
    const float* W1_0_w     = (const float*)d_in[3];
    const float* W1_0_b     = (const float*)d_in[4];
    const float* W2_0_w     = (const float*)d_in[5];
    const float* W2_0_b     = (const float*)d_in[6];
    const float* W1_1_w     = (const float*)d_in[7];
    const float* W1_1_b     = (const float*)d_in[8];
    const float* W2_1_w     = (const float*)d_in[9];
    const float* W2_1_b     = (const float*)d_in[10];
    const int*   src        = (const int*)d_in[11];
    const int*   dst        = (const int*)d_in[12];
    const int*   et         = (const int*)d_in[13];
    float* out = (float*)d_out;

    const int SM_PROJ  = (128 * PITCH + 64 * PITCH) * 4;       // 55296 B
    const int SM_MLP0  = (2 * 128 * PITCH + 2 * 64 * PITCH) * 4; // 110592 B
    const int SM_MLP1  = (2 * 64 * 36 + 2 * 64 * 68) * 4;      // 53248 B
    cudaFuncSetAttribute(k_projmma, cudaFuncAttributeMaxDynamicSharedMemorySize, SM_PROJ);
    cudaFuncSetAttribute(k_mlp0mma, cudaFuncAttributeMaxDynamicSharedMemorySize, SM_MLP0);
    cudaFuncSetAttribute(k_mlp1, cudaFuncAttributeMaxDynamicSharedMemorySize, SM_MLP1);

    // CSR build (counting sort by dst)
    k_init<<<(N_ENT + 255) / 256, 256>>>();
    k_hist<<<(NE + 255) / 256, 256>>>(dst);
    k_scan1<<<NSCAN, 1024>>>();
    k_scan2<<<1, 128>>>();
    k_scan3<<<(N_ENT + 255) / 256, 256>>>();
    k_fill<<<(NE + 255) / 256, 256>>>(src, dst, et);

    // proj via mma.sync tf32 (fp16 output), CSR-ordered logits
    k_prepW<<<(N_REL * DD * DD + 255) / 256, 256>>>(W_r);
    k_prepWm<<<(2 * DD * DD + 255) / 256, 256>>>(W1_0_w, W2_0_w);
    k_projmma<<<NTILES_M, 256, SM_PROJ>>>(entity_emb);
    k_logits<<<NE / 8, 256>>>(rel_emb);

    // layer 0 (fused softmax + gather, then MMA MLP)
    k_attgather<<<(N_ENT + 7) / 8, 256>>>(entity_emb);
    k_mlp0mma<<<NTILES_M, 256, SM_MLP0>>>(entity_emb, W1_0_b, W2_0_b, out);

    // layer 1
    k_gather1<<<(N_ENT + 7) / 8, 256>>>(out + 64);
    k_mlp1<<<512, 256, SM_MLP1>>>(W1_1_w, W1_1_b, W2_1_w, W2_1_b, out);
}